// round 10
// baseline (speedup 1.0000x reference)
#include <cuda_runtime.h>
#include <math.h>
#include <stddef.h>
#include <stdint.h>

// MLA shapes (compile-time constants)
#define B_    2
#define S_    2048
#define H_    2048
#define NH_   16
#define QL_   1536
#define KVL_  512
#define NOPE_ 128
#define ROPE_ 64
#define VD_   128
#define QKH_  192
#define ROWS_ (B_*S_)   // 4096

// ---------------- scratch (device globals: no allocs allowed) ----------------
__device__ float g_qa  [(size_t)ROWS_*QL_];
__device__ float g_q   [(size_t)ROWS_*NH_*QKH_];
__device__ float g_kvf [(size_t)ROWS_*(KVL_+ROPE_)];
__device__ float g_kvn [(size_t)ROWS_*KVL_];
__device__ float g_kpe [(size_t)ROWS_*ROPE_];
__device__ float g_kvab[(size_t)B_*NH_*S_*256];
__device__ float g_att [(size_t)ROWS_*NH_*VD_];
__device__ float g_cos [(size_t)S_*ROPE_];
__device__ float g_sin [(size_t)S_*ROPE_];

// ---------------- tf32 helpers ----------------
__device__ __forceinline__ uint32_t f2tf(float x) {
    uint32_t r;
    asm("cvt.rna.tf32.f32 %0, %1;" : "=r"(r) : "f"(x));
    return r;
}

#define MMA_TF32(d, a0, a1, a2, a3, b0, b1)                                  \
    asm volatile(                                                            \
        "mma.sync.aligned.m16n8k8.row.col.f32.tf32.tf32.f32 "                \
        "{%0,%1,%2,%3}, {%4,%5,%6,%7}, {%8,%9}, {%0,%1,%2,%3};"              \
        : "+f"((d)[0]), "+f"((d)[1]), "+f"((d)[2]), "+f"((d)[3])             \
        : "r"(a0), "r"(a1), "r"(a2), "r"(a3), "r"(b0), "r"(b1))

// K-permutation: element with orig k-index k within its 8-group is stored at
// (k&~7) | ((k&3)*2 + ((k>>2)&1)); then a thread's fragment pair (k, k+4)
// sits at consecutive words (2*tg, 2*tg+1) -> one LDS.64, conflict-free when
// the row stride is ==8 (mod 32).

// ---------------- tensor-core GEMM: C = A(MxK) @ W(NxK)^T + bias ------------
// tf32 mma.sync m16n8k8, fp32 accumulate. 128x128 block tile, BK=32,
// 256 threads = 8 warps in 2x4 (warp tile 64x32 -> 4x4 m16n8 tiles).
// Double-buffered smem + register prefetch: 1 sync/iter, LDG hidden by MMA.
// Smem tile stride 40 words (==8 mod 32) -> LDS.64 frag loads conflict-free.
__global__ void __launch_bounds__(256, 2) sgemm_bias(
    const float* __restrict__ A, const float* __restrict__ W,
    const float* __restrict__ bias, float* __restrict__ C,
    int M, int N, int K,
    int zdA, long long sA, int zmB, long long sB, long long sC)
{
    extern __shared__ uint32_t sg[];   // 2 buffers x (A 128*40 + B 128*40)

    const int z = blockIdx.z;
    A += (long long)(z / zdA) * sA;
    W += (long long)(z % zmB) * sB;
    C += (long long)z * sC;

    const int tid  = threadIdx.x;
    const int warp = tid >> 5, lane = tid & 31;
    const int wm = warp >> 2;
    const int wn = warp & 3;
    const int g  = lane >> 2;
    const int tg = lane & 3;
    const int m0 = blockIdx.y * 128;
    const int n0 = blockIdx.x * 128;

    float acc[4][4][4];
#pragma unroll
    for (int mt = 0; mt < 4; mt++)
#pragma unroll
        for (int nt = 0; nt < 4; nt++)
#pragma unroll
            for (int r = 0; r < 4; r++) acc[mt][nt][r] = 0.f;

    float4 pa[4], pb[4];

    // prefetch tile k0 into registers
    auto prefetch = [&](int k0) {
#pragma unroll
        for (int it = 0; it < 4; it++) {
            int idx = tid + it * 256;
            int r = idx >> 3;
            int c = (idx & 7) << 2;
            pa[it] = *reinterpret_cast<const float4*>(A + (size_t)(m0 + r) * K + k0 + c);
            int n = n0 + r;
            pb[it] = (n < N)
                ? *reinterpret_cast<const float4*>(W + (size_t)n * K + k0 + c)
                : make_float4(0.f, 0.f, 0.f, 0.f);
        }
    };
    // convert + store prefetched tile into buffer bsel (k-permuted layout)
    auto store_tile = [&](int bsel) {
        uint32_t* Ab = sg + bsel * 10240;
        uint32_t* Bb = Ab + 5120;
#pragma unroll
        for (int it = 0; it < 4; it++) {
            int idx = tid + it * 256;
            int r = idx >> 3;
            int c = (idx & 7) << 2;
            int base = (c >> 3) * 8 + ((c >> 2) & 1);
            uint32_t* d = Ab + r * 40 + base;
            d[0] = f2tf(pa[it].x); d[2] = f2tf(pa[it].y);
            d[4] = f2tf(pa[it].z); d[6] = f2tf(pa[it].w);
            uint32_t* e = Bb + r * 40 + base;
            e[0] = f2tf(pb[it].x); e[2] = f2tf(pb[it].y);
            e[4] = f2tf(pb[it].z); e[6] = f2tf(pb[it].w);
        }
    };

    const int nk = K >> 5;
    prefetch(0);
    store_tile(0);
    __syncthreads();

    for (int kb = 0; kb < nk; kb++) {
        if (kb + 1 < nk) prefetch((kb + 1) << 5);

        const uint32_t* Ab = sg + (kb & 1) * 10240;
        const uint32_t* Bb = Ab + 5120;
#pragma unroll
        for (int ks = 0; ks < 4; ks++) {
            const int kb8 = ks * 8 + 2 * tg;
            uint32_t af[4][4], bf[4][2];
#pragma unroll
            for (int mt = 0; mt < 4; mt++) {
                int rb = wm * 64 + mt * 16 + g;
                uint2 lo = *reinterpret_cast<const uint2*>(Ab + rb * 40 + kb8);
                uint2 hi = *reinterpret_cast<const uint2*>(Ab + (rb + 8) * 40 + kb8);
                af[mt][0] = lo.x; af[mt][1] = hi.x; af[mt][2] = lo.y; af[mt][3] = hi.y;
            }
#pragma unroll
            for (int nt = 0; nt < 4; nt++) {
                uint2 bb = *reinterpret_cast<const uint2*>(Bb + (wn * 32 + nt * 8 + g) * 40 + kb8);
                bf[nt][0] = bb.x; bf[nt][1] = bb.y;
            }
#pragma unroll
            for (int mt = 0; mt < 4; mt++)
#pragma unroll
                for (int nt = 0; nt < 4; nt++)
                    MMA_TF32(acc[mt][nt], af[mt][0], af[mt][1], af[mt][2], af[mt][3],
                             bf[nt][0], bf[nt][1]);
        }

        if (kb + 1 < nk) store_tile((kb + 1) & 1);
        __syncthreads();
    }

#pragma unroll
    for (int mt = 0; mt < 4; mt++) {
        int row = m0 + wm * 64 + mt * 16 + g;
#pragma unroll
        for (int nt = 0; nt < 4; nt++) {
            int col = n0 + wn * 32 + nt * 8 + (tg << 1);
            if (col < N) {
                float2 bv = make_float2(0.f, 0.f);
                if (bias) bv = *reinterpret_cast<const float2*>(bias + col);
                float2 v0 = make_float2(acc[mt][nt][0] + bv.x, acc[mt][nt][1] + bv.y);
                float2 v1 = make_float2(acc[mt][nt][2] + bv.x, acc[mt][nt][3] + bv.y);
                *reinterpret_cast<float2*>(C + (size_t)row * N + col) = v0;
                *reinterpret_cast<float2*>(C + (size_t)(row + 8) * N + col) = v1;
            }
        }
    }
}

// ---------------- RMSNorm (in-place), one block per row --------------------
__global__ void __launch_bounds__(256) rmsnorm_k(float* __restrict__ x,
                                                 const float* __restrict__ w, int D)
{
    const int row = blockIdx.x;
    float* xr = x + (size_t)row * D;
    float ss = 0.f;
    for (int i = threadIdx.x; i < D; i += 256) { float v = xr[i]; ss = fmaf(v, v, ss); }
    __shared__ float red[8];
#pragma unroll
    for (int d = 16; d; d >>= 1) ss += __shfl_xor_sync(0xffffffffu, ss, d);
    if ((threadIdx.x & 31) == 0) red[threadIdx.x >> 5] = ss;
    __syncthreads();
    if (threadIdx.x == 0) {
        float t = 0.f;
#pragma unroll
        for (int i = 0; i < 8; i++) t += red[i];
        red[0] = t;
    }
    __syncthreads();
    const float r = rsqrtf(red[0] / (float)D + 1e-6f);
    for (int i = threadIdx.x; i < D; i += 256) xr[i] = w[i] * (xr[i] * r);
}

// ---------------- RoPE tables (fp64 trig for range safety) ------------------
__global__ void rope_tab_k(float* __restrict__ ct, float* __restrict__ st)
{
    const int pos = blockIdx.x;
    const int j = threadIdx.x;
    double inv = pow(10000.0, -((double)j) / 32.0);
    float ang = (float)pos * (float)inv;
    float c = (float)cos((double)ang);
    float s = (float)sin((double)ang);
    ct[pos * 64 + j] = c; ct[pos * 64 + j + 32] = c;
    st[pos * 64 + j] = s; st[pos * 64 + j + 32] = s;
}

// ---------------- kv split: rmsnorm first 512, rope last 64 -----------------
__global__ void __launch_bounds__(256) kvprep_k(
    const float* __restrict__ kvf, const float* __restrict__ w,
    float* __restrict__ kvn, float* __restrict__ kpe,
    const float* __restrict__ ct, const float* __restrict__ st)
{
    const int row = blockIdx.x;
    const float* xr = kvf + (size_t)row * 576;
    float ss = 0.f;
    for (int i = threadIdx.x; i < 512; i += 256) { float v = xr[i]; ss = fmaf(v, v, ss); }
    __shared__ float red[8];
#pragma unroll
    for (int d = 16; d; d >>= 1) ss += __shfl_xor_sync(0xffffffffu, ss, d);
    if ((threadIdx.x & 31) == 0) red[threadIdx.x >> 5] = ss;
    __syncthreads();
    if (threadIdx.x == 0) {
        float t = 0.f;
#pragma unroll
        for (int i = 0; i < 8; i++) t += red[i];
        red[0] = t;
    }
    __syncthreads();
    const float r = rsqrtf(red[0] / 512.f + 1e-6f);
    for (int i = threadIdx.x; i < 512; i += 256)
        kvn[(size_t)row * 512 + i] = w[i] * (xr[i] * r);

    if (threadIdx.x < 32) {
        const int j = threadIdx.x;
        const int pos = row & (S_ - 1);
        float c = ct[pos * 64 + j], s = st[pos * 64 + j];
        float x1 = xr[512 + j], x2 = xr[544 + j];
        kpe[(size_t)row * 64 + j]      = x1 * c - x2 * s;
        kpe[(size_t)row * 64 + 32 + j] = x2 * c + x1 * s;
    }
}

// ---------------- rope on q_pe slice of each head (in-place) ----------------
__global__ void __launch_bounds__(256) ropeq_k(float* __restrict__ q,
                                               const float* __restrict__ ct,
                                               const float* __restrict__ st)
{
    const int idx = blockIdx.x * 256 + threadIdx.x;
    const int row = idx >> 9;
    const int h = (idx >> 5) & 15;
    const int j = idx & 31;
    const int pos = row & (S_ - 1);
    float* p = q + (size_t)row * 3072 + h * 192 + 128;
    float c = ct[pos * 64 + j], s = st[pos * 64 + j];
    float x1 = p[j], x2 = p[j + 32];
    p[j]      = x1 * c - x2 * s;
    p[j + 32] = x2 * c + x1 * s;
}

// ---------------- flash attention (absorbed MLA) on tensor cores ------------
// qk-dim 192 (128 k_abs + 64 k_pe), v-dim 128; tf32 mma m16n8k8, fp32 softmax.
// K-permuted smem layouts -> LDS.64 fragment feeds, conflict-free
// (strides 200 and 72 are ==8 mod 32).
__global__ void __launch_bounds__(256) attn_k(
    const float* __restrict__ Q,    // [4096, 3072]
    const float* __restrict__ KV,   // [32][2048][256]: k_abs | v_abs
    const float* __restrict__ Kpe,  // [4096, 64]
    const int*   __restrict__ msk,  // [2, 2048]
    float* __restrict__ Out)        // [4096, 2048]
{
    const int qb = blockIdx.x, h = blockIdx.y, b = blockIdx.z;
    const int tid = threadIdx.x;
    const int warp = tid >> 5, lane = tid & 31;
    const int wm = warp >> 1, wn = warp & 1;
    const int g = lane >> 2, tg = lane & 3;

    extern __shared__ uint32_t smu[];
    uint32_t* sQ  = smu;                 // [64][200] tf32, k-permuted cols
    uint32_t* sK  = sQ + 64 * 200;       // [64][200]
    uint32_t* sVT = sK + 64 * 200;       // [128][72] (V transposed, k-permuted rows)
    uint32_t* sP  = sVT + 128 * 72;      // [64][72]
    float* sM = (float*)(sP + 64 * 72);  // [2][64]
    float* sS = sM + 128;                // [2][64]

    const int s0 = qb * 64;
    const float* Qb = Q + (size_t)(b * 2048 + s0) * 3072 + h * 192;
    for (int idx = tid; idx < 64 * 48; idx += 256) {
        int r = idx / 48, c4 = idx % 48;
        float4 v = *reinterpret_cast<const float4*>(Qb + (size_t)r * 3072 + c4 * 4);
        int c = c4 * 4;
        uint32_t* d = sQ + r * 200 + (c >> 3) * 8 + ((c >> 2) & 1);
        d[0] = f2tf(v.x); d[2] = f2tf(v.y); d[4] = f2tf(v.z); d[6] = f2tf(v.w);
    }

    const float scale = 0.07216878364870322f;  // 1/sqrt(192)
    const int r1 = wm * 16 + g, r2 = r1 + 8;
    const int sg1 = s0 + r1, sg2 = s0 + r2;
    // permuted positions of within-8 k-indices 2tg and 2tg+1 (for P store)
    const int pos0 = ((2 * tg) & 3) * 2 + (tg >> 1);
    const int pos1 = ((2 * tg + 1) & 3) * 2 + (tg >> 1);

    float m1 = -3.0e38f, m2 = -3.0e38f, l1 = 0.f, l2 = 0.f;
    float o[8][4];
#pragma unroll
    for (int nt = 0; nt < 8; nt++)
#pragma unroll
        for (int r = 0; r < 4; r++) o[nt][r] = 0.f;

    const int* mrow = msk + (size_t)b * 2048;

    for (int kt = 0; kt <= qb; kt++) {
        __syncthreads();
        const float* KVb = KV + ((size_t)(b * 16 + h) * 2048 + kt * 64) * 256;
        for (int idx = tid; idx < 64 * 64; idx += 256) {
            int r = idx >> 6, c4 = idx & 63;
            float4 v = *reinterpret_cast<const float4*>(KVb + (size_t)r * 256 + c4 * 4);
            if (c4 < 32) {
                int c = c4 * 4;
                uint32_t* d = sK + r * 200 + (c >> 3) * 8 + ((c >> 2) & 1);
                d[0] = f2tf(v.x); d[2] = f2tf(v.y); d[4] = f2tf(v.z); d[6] = f2tf(v.w);
            } else {
                int vc = (c4 - 32) * 4;
                int pr = (r & ~7) | (((r & 3) << 1) | ((r >> 2) & 1));
                sVT[(vc + 0) * 72 + pr] = f2tf(v.x);
                sVT[(vc + 1) * 72 + pr] = f2tf(v.y);
                sVT[(vc + 2) * 72 + pr] = f2tf(v.z);
                sVT[(vc + 3) * 72 + pr] = f2tf(v.w);
            }
        }
        const float* Kpb = Kpe + (size_t)(b * 2048 + kt * 64) * 64;
        for (int idx = tid; idx < 64 * 16; idx += 256) {
            int r = idx >> 4, c4 = idx & 15;
            float4 v = *reinterpret_cast<const float4*>(Kpb + (size_t)r * 64 + c4 * 4);
            int c = 128 + c4 * 4;
            uint32_t* d = sK + r * 200 + (c >> 3) * 8 + ((c >> 2) & 1);
            d[0] = f2tf(v.x); d[2] = f2tf(v.y); d[4] = f2tf(v.z); d[6] = f2tf(v.w);
        }
        __syncthreads();

        // ---- scores: 16x32 per warp over 192-dim contraction ----
        float sc[4][4];
#pragma unroll
        for (int nt = 0; nt < 4; nt++)
#pragma unroll
            for (int r = 0; r < 4; r++) sc[nt][r] = 0.f;

#pragma unroll
        for (int ks = 0; ks < 24; ks++) {
            const int kb8 = ks * 8 + 2 * tg;
            uint2 lo = *reinterpret_cast<const uint2*>(sQ + r1 * 200 + kb8);
            uint2 hi = *reinterpret_cast<const uint2*>(sQ + r2 * 200 + kb8);
#pragma unroll
            for (int nt = 0; nt < 4; nt++) {
                uint2 bb = *reinterpret_cast<const uint2*>(sK + (wn * 32 + nt * 8 + g) * 200 + kb8);
                MMA_TF32(sc[nt], lo.x, hi.x, lo.y, hi.y, bb.x, bb.y);
            }
        }

        // ---- scale + mask + row max ----
        const bool diag = (kt == qb);
        float tm1 = -3.0e38f, tm2 = -3.0e38f;
#pragma unroll
        for (int nt = 0; nt < 4; nt++) {
            int t0 = kt * 64 + wn * 32 + nt * 8 + 2 * tg, t1 = t0 + 1;
            int mv0 = mrow[t0], mv1 = mrow[t1];
            float v0 = sc[nt][0] * scale; if ((diag && t0 > sg1) || mv0 == 0) v0 = -1e15f;
            float v1 = sc[nt][1] * scale; if ((diag && t1 > sg1) || mv1 == 0) v1 = -1e15f;
            float v2 = sc[nt][2] * scale; if ((diag && t0 > sg2) || mv0 == 0) v2 = -1e15f;
            float v3 = sc[nt][3] * scale; if ((diag && t1 > sg2) || mv1 == 0) v3 = -1e15f;
            sc[nt][0] = v0; sc[nt][1] = v1; sc[nt][2] = v2; sc[nt][3] = v3;
            tm1 = fmaxf(tm1, fmaxf(v0, v1));
            tm2 = fmaxf(tm2, fmaxf(v2, v3));
        }
        tm1 = fmaxf(tm1, __shfl_xor_sync(0xffffffffu, tm1, 1));
        tm1 = fmaxf(tm1, __shfl_xor_sync(0xffffffffu, tm1, 2));
        tm2 = fmaxf(tm2, __shfl_xor_sync(0xffffffffu, tm2, 1));
        tm2 = fmaxf(tm2, __shfl_xor_sync(0xffffffffu, tm2, 2));
        if (tg == 0) { sM[wn * 64 + r1] = tm1; sM[wn * 64 + r2] = tm2; }
        __syncthreads();

        float nm1 = fmaxf(m1, fmaxf(sM[r1], sM[64 + r1]));
        float nm2 = fmaxf(m2, fmaxf(sM[r2], sM[64 + r2]));
        float al1 = expf(m1 - nm1), al2 = expf(m2 - nm2);
        m1 = nm1; m2 = nm2;

        // ---- exp + P store (tf32, k-permuted) + row sum ----
        float ls1 = 0.f, ls2 = 0.f;
#pragma unroll
        for (int nt = 0; nt < 4; nt++) {
            float p0 = expf(sc[nt][0] - nm1);
            float p1 = expf(sc[nt][1] - nm1);
            float p2 = expf(sc[nt][2] - nm2);
            float p3 = expf(sc[nt][3] - nm2);
            ls1 += p0 + p1; ls2 += p2 + p3;
            int base = wn * 32 + nt * 8;
            sP[r1 * 72 + base + pos0] = f2tf(p0);
            sP[r1 * 72 + base + pos1] = f2tf(p1);
            sP[r2 * 72 + base + pos0] = f2tf(p2);
            sP[r2 * 72 + base + pos1] = f2tf(p3);
        }
        ls1 += __shfl_xor_sync(0xffffffffu, ls1, 1);
        ls1 += __shfl_xor_sync(0xffffffffu, ls1, 2);
        ls2 += __shfl_xor_sync(0xffffffffu, ls2, 1);
        ls2 += __shfl_xor_sync(0xffffffffu, ls2, 2);
        if (tg == 0) { sS[wn * 64 + r1] = ls1; sS[wn * 64 + r2] = ls2; }
        __syncthreads();

        l1 = l1 * al1 + sS[r1] + sS[64 + r1];
        l2 = l2 * al2 + sS[r2] + sS[64 + r2];

        // ---- O rescale + PV: 16x64 per warp over 64-dim contraction ----
#pragma unroll
        for (int nt = 0; nt < 8; nt++) {
            o[nt][0] *= al1; o[nt][1] *= al1; o[nt][2] *= al2; o[nt][3] *= al2;
        }
#pragma unroll
        for (int ks = 0; ks < 8; ks++) {
            const int kb8 = ks * 8 + 2 * tg;
            uint2 lo = *reinterpret_cast<const uint2*>(sP + r1 * 72 + kb8);
            uint2 hi = *reinterpret_cast<const uint2*>(sP + r2 * 72 + kb8);
#pragma unroll
            for (int nt = 0; nt < 8; nt++) {
                uint2 bb = *reinterpret_cast<const uint2*>(sVT + (wn * 64 + nt * 8 + g) * 72 + kb8);
                MMA_TF32(o[nt], lo.x, hi.x, lo.y, hi.y, bb.x, bb.y);
            }
        }
    }

    // ---- epilogue ----
    const float i1 = 1.f / l1, i2 = 1.f / l2;
    float* orow1 = Out + (size_t)(b * 2048 + sg1) * 2048 + h * 128;
    float* orow2 = Out + (size_t)(b * 2048 + sg2) * 2048 + h * 128;
#pragma unroll
    for (int nt = 0; nt < 8; nt++) {
        int c = wn * 64 + nt * 8 + 2 * tg;
        *reinterpret_cast<float2*>(orow1 + c) = make_float2(o[nt][0] * i1, o[nt][1] * i1);
        *reinterpret_cast<float2*>(orow2 + c) = make_float2(o[nt][2] * i2, o[nt][3] * i2);
    }
}

// ------------------------------- host side ---------------------------------
extern "C" void kernel_launch(void* const* d_in, const int* in_sizes, int n_in,
                              void* d_out, int out_size)
{
    (void)in_sizes; (void)n_in; (void)out_size;
    const float* x        = (const float*)d_in[0];
    const int*   mask     = (const int*)  d_in[1];
    const float* wq_a_w   = (const float*)d_in[2];
    const float* wq_a_b   = (const float*)d_in[3];
    const float* q_norm_w = (const float*)d_in[4];
    const float* wq_b_w   = (const float*)d_in[5];
    const float* wq_b_b   = (const float*)d_in[6];
    const float* wkv_a_w  = (const float*)d_in[7];
    const float* wkv_a_b  = (const float*)d_in[8];
    const float* kv_norm_w= (const float*)d_in[9];
    const float* wkv_b_w  = (const float*)d_in[10];
    const float* wo_w     = (const float*)d_in[11];
    const float* wo_b     = (const float*)d_in[12];
    float* out = (float*)d_out;

    float *qa, *q, *kvf, *kvn, *kpe, *kvab, *att, *ct, *st;
    cudaGetSymbolAddress((void**)&qa,   g_qa);
    cudaGetSymbolAddress((void**)&q,    g_q);
    cudaGetSymbolAddress((void**)&kvf,  g_kvf);
    cudaGetSymbolAddress((void**)&kvn,  g_kvn);
    cudaGetSymbolAddress((void**)&kpe,  g_kpe);
    cudaGetSymbolAddress((void**)&kvab, g_kvab);
    cudaGetSymbolAddress((void**)&att,  g_att);
    cudaGetSymbolAddress((void**)&ct,   g_cos);
    cudaGetSymbolAddress((void**)&st,   g_sin);

    const int gemm_smem = 2 * 10240 * 4;   // 81,920 B
    cudaFuncSetAttribute(sgemm_bias, cudaFuncAttributeMaxDynamicSharedMemorySize, gemm_smem);

    rope_tab_k<<<S_, 32>>>(ct, st);

    // q_a = x @ wq_a^T + b   [4096,2048]x[1536,2048]
    { dim3 g(QL_ / 128, ROWS_ / 128, 1);
      sgemm_bias<<<g, 256, gemm_smem>>>(x, wq_a_w, wq_a_b, qa, ROWS_, QL_, H_, 1, 0, 1, 0, 0); }
    rmsnorm_k<<<ROWS_, 256>>>(qa, q_norm_w, QL_);
    // q = q_a @ wq_b^T + b   [4096,1536]x[3072,1536]
    { dim3 g((NH_ * QKH_) / 128, ROWS_ / 128, 1);
      sgemm_bias<<<g, 256, gemm_smem>>>(qa, wq_b_w, wq_b_b, q, ROWS_, NH_ * QKH_, QL_, 1, 0, 1, 0, 0); }
    // kv_full = x @ wkv_a^T + b   [4096,2048]x[576,2048]
    { dim3 g((KVL_ + ROPE_ + 127) / 128, ROWS_ / 128, 1);
      sgemm_bias<<<g, 256, gemm_smem>>>(x, wkv_a_w, wkv_a_b, kvf, ROWS_, KVL_ + ROPE_, H_, 1, 0, 1, 0, 0); }
    kvprep_k<<<ROWS_, 256>>>(kvf, kv_norm_w, kvn, kpe, ct, st);
    ropeq_k<<<(ROWS_ * NH_ * 32) / 256, 256>>>(q, ct, st);

    // absorbed K/V: per (b,h): kvab[z] = kvn[b] (2048x512) @ wkv_b[h] (256x512)^T
    { dim3 g(256 / 128, S_ / 128, B_ * NH_);
      sgemm_bias<<<g, 256, gemm_smem>>>(kvn, wkv_b_w, nullptr, kvab, S_, 256, KVL_,
                             NH_, (long long)S_ * KVL_,
                             NH_, 256LL * KVL_,
                             (long long)S_ * 256); }

    // flash attention (tensor-core, LDS.64 frag feeds)
    const int attn_smem = (64 * 200 * 2 + 128 * 72 + 64 * 72 + 256) * 4;  // 158,720 B
    cudaFuncSetAttribute(attn_k, cudaFuncAttributeMaxDynamicSharedMemorySize, attn_smem);
    attn_k<<<dim3(S_ / 64, NH_, B_), 256, attn_smem>>>(q, kvab, kpe, mask, att);

    // out = att @ wo^T + b   [4096,2048]x[2048,2048]
    { dim3 g(H_ / 128, ROWS_ / 128, 1);
      sgemm_bias<<<g, 256, gemm_smem>>>(att, wo_w, wo_b, out, ROWS_, H_, NH_ * VD_, 1, 0, 1, 0, 0); }
}

// round 11
// speedup vs baseline: 1.0069x; 1.0069x over previous
#include <cuda_runtime.h>
#include <math.h>
#include <stddef.h>
#include <stdint.h>

// MLA shapes (compile-time constants)
#define B_    2
#define S_    2048
#define H_    2048
#define NH_   16
#define QL_   1536
#define KVL_  512
#define NOPE_ 128
#define ROPE_ 64
#define VD_   128
#define QKH_  192
#define ROWS_ (B_*S_)   // 4096

// ---------------- scratch (device globals: no allocs allowed) ----------------
__device__ float g_qa  [(size_t)ROWS_*QL_];
__device__ float g_q   [(size_t)ROWS_*NH_*QKH_];
__device__ float g_kvf [(size_t)ROWS_*(KVL_+ROPE_)];
__device__ float g_kvn [(size_t)ROWS_*KVL_];
__device__ float g_kpe [(size_t)ROWS_*ROPE_];
__device__ float g_kvab[(size_t)B_*NH_*S_*256];
__device__ float g_att [(size_t)ROWS_*NH_*VD_];
__device__ float g_cos [(size_t)S_*ROPE_];
__device__ float g_sin [(size_t)S_*ROPE_];

// ---------------- tf32 helpers ----------------
__device__ __forceinline__ uint32_t f2tf(float x) {
    uint32_t r;
    asm("cvt.rna.tf32.f32 %0, %1;" : "=r"(r) : "f"(x));
    return r;
}

#define MMA_TF32(d, a0, a1, a2, a3, b0, b1)                                  \
    asm volatile(                                                            \
        "mma.sync.aligned.m16n8k8.row.col.f32.tf32.tf32.f32 "                \
        "{%0,%1,%2,%3}, {%4,%5,%6,%7}, {%8,%9}, {%0,%1,%2,%3};"              \
        : "+f"((d)[0]), "+f"((d)[1]), "+f"((d)[2]), "+f"((d)[3])             \
        : "r"(a0), "r"(a1), "r"(a2), "r"(a3), "r"(b0), "r"(b1))

// K-permutation: k-index k stored at (k&~7) | ((k&3)*2 + ((k>>2)&1)); the
// fragment pair (k, k+4) for thread-group tg becomes words (2tg, 2tg+1):
// one LDS.64, conflict-free when the row stride is ==8 (mod 32).

// ---------------- tensor-core GEMM: C = A(MxK) @ W(NxK)^T + bias ------------
// tf32 mma.sync m16n8k8, fp32 accumulate. 128x128 block tile, BK=32,
// 256 threads = 8 warps in 2x4 (warp tile 64x32 -> 4x4 m16n8 tiles).
// Single-buffered smem (nothing lives across the MMA block -> no spills),
// k-permuted layout with stride 40 (==8 mod 32) -> LDS.64 conflict-free.
__global__ void __launch_bounds__(256, 2) sgemm_bias(
    const float* __restrict__ A, const float* __restrict__ W,
    const float* __restrict__ bias, float* __restrict__ C,
    int M, int N, int K,
    int zdA, long long sA, int zmB, long long sB, long long sC)
{
    __shared__ __align__(16) uint32_t As[128][40];
    __shared__ __align__(16) uint32_t Bs[128][40];

    const int z = blockIdx.z;
    A += (long long)(z / zdA) * sA;
    W += (long long)(z % zmB) * sB;
    C += (long long)z * sC;

    const int tid  = threadIdx.x;
    const int warp = tid >> 5, lane = tid & 31;
    const int wm = warp >> 2;
    const int wn = warp & 3;
    const int g  = lane >> 2;
    const int tg = lane & 3;
    const int m0 = blockIdx.y * 128;
    const int n0 = blockIdx.x * 128;

    float acc[4][4][4];
#pragma unroll
    for (int mt = 0; mt < 4; mt++)
#pragma unroll
        for (int nt = 0; nt < 4; nt++)
#pragma unroll
            for (int r = 0; r < 4; r++) acc[mt][nt][r] = 0.f;

    for (int k0 = 0; k0 < K; k0 += 32) {
#pragma unroll
        for (int it = 0; it < 4; it++) {
            int idx = tid + it * 256;
            int r = idx >> 3;
            int c = (idx & 7) << 2;
            int base = (c & ~7) | ((c >> 2) & 1);
            float4 va = *reinterpret_cast<const float4*>(A + (size_t)(m0 + r) * K + k0 + c);
            uint32_t* d = &As[r][base];
            d[0] = f2tf(va.x); d[2] = f2tf(va.y); d[4] = f2tf(va.z); d[6] = f2tf(va.w);
            int n = n0 + r;
            float4 vb = (n < N)
                ? *reinterpret_cast<const float4*>(W + (size_t)n * K + k0 + c)
                : make_float4(0.f, 0.f, 0.f, 0.f);
            uint32_t* e = &Bs[r][base];
            e[0] = f2tf(vb.x); e[2] = f2tf(vb.y); e[4] = f2tf(vb.z); e[6] = f2tf(vb.w);
        }
        __syncthreads();

#pragma unroll
        for (int ks = 0; ks < 4; ks++) {
            const int kb8 = ks * 8 + 2 * tg;
            uint32_t af[4][4], bf[4][2];
#pragma unroll
            for (int mt = 0; mt < 4; mt++) {
                int rb = wm * 64 + mt * 16 + g;
                uint2 lo = *reinterpret_cast<const uint2*>(&As[rb][kb8]);
                uint2 hi = *reinterpret_cast<const uint2*>(&As[rb + 8][kb8]);
                af[mt][0] = lo.x; af[mt][1] = hi.x; af[mt][2] = lo.y; af[mt][3] = hi.y;
            }
#pragma unroll
            for (int nt = 0; nt < 4; nt++) {
                uint2 bb = *reinterpret_cast<const uint2*>(&Bs[wn * 32 + nt * 8 + g][kb8]);
                bf[nt][0] = bb.x; bf[nt][1] = bb.y;
            }
#pragma unroll
            for (int mt = 0; mt < 4; mt++)
#pragma unroll
                for (int nt = 0; nt < 4; nt++)
                    MMA_TF32(acc[mt][nt], af[mt][0], af[mt][1], af[mt][2], af[mt][3],
                             bf[nt][0], bf[nt][1]);
        }
        __syncthreads();
    }

#pragma unroll
    for (int mt = 0; mt < 4; mt++) {
        int row = m0 + wm * 64 + mt * 16 + g;
#pragma unroll
        for (int nt = 0; nt < 4; nt++) {
            int col = n0 + wn * 32 + nt * 8 + (tg << 1);
            if (col < N) {
                float2 bv = make_float2(0.f, 0.f);
                if (bias) bv = *reinterpret_cast<const float2*>(bias + col);
                float2 v0 = make_float2(acc[mt][nt][0] + bv.x, acc[mt][nt][1] + bv.y);
                float2 v1 = make_float2(acc[mt][nt][2] + bv.x, acc[mt][nt][3] + bv.y);
                *reinterpret_cast<float2*>(C + (size_t)row * N + col) = v0;
                *reinterpret_cast<float2*>(C + (size_t)(row + 8) * N + col) = v1;
            }
        }
    }
}

// ---------------- RMSNorm (in-place), one block per row --------------------
__global__ void __launch_bounds__(256) rmsnorm_k(float* __restrict__ x,
                                                 const float* __restrict__ w, int D)
{
    const int row = blockIdx.x;
    float* xr = x + (size_t)row * D;
    float ss = 0.f;
    for (int i = threadIdx.x; i < D; i += 256) { float v = xr[i]; ss = fmaf(v, v, ss); }
    __shared__ float red[8];
#pragma unroll
    for (int d = 16; d; d >>= 1) ss += __shfl_xor_sync(0xffffffffu, ss, d);
    if ((threadIdx.x & 31) == 0) red[threadIdx.x >> 5] = ss;
    __syncthreads();
    if (threadIdx.x == 0) {
        float t = 0.f;
#pragma unroll
        for (int i = 0; i < 8; i++) t += red[i];
        red[0] = t;
    }
    __syncthreads();
    const float r = rsqrtf(red[0] / (float)D + 1e-6f);
    for (int i = threadIdx.x; i < D; i += 256) xr[i] = w[i] * (xr[i] * r);
}

// ---------------- RoPE tables (fp64 trig for range safety) ------------------
__global__ void rope_tab_k(float* __restrict__ ct, float* __restrict__ st)
{
    const int pos = blockIdx.x;
    const int j = threadIdx.x;
    double inv = pow(10000.0, -((double)j) / 32.0);
    float ang = (float)pos * (float)inv;
    float c = (float)cos((double)ang);
    float s = (float)sin((double)ang);
    ct[pos * 64 + j] = c; ct[pos * 64 + j + 32] = c;
    st[pos * 64 + j] = s; st[pos * 64 + j + 32] = s;
}

// ---------------- kv split: rmsnorm first 512, rope last 64 -----------------
__global__ void __launch_bounds__(256) kvprep_k(
    const float* __restrict__ kvf, const float* __restrict__ w,
    float* __restrict__ kvn, float* __restrict__ kpe,
    const float* __restrict__ ct, const float* __restrict__ st)
{
    const int row = blockIdx.x;
    const float* xr = kvf + (size_t)row * 576;
    float ss = 0.f;
    for (int i = threadIdx.x; i < 512; i += 256) { float v = xr[i]; ss = fmaf(v, v, ss); }
    __shared__ float red[8];
#pragma unroll
    for (int d = 16; d; d >>= 1) ss += __shfl_xor_sync(0xffffffffu, ss, d);
    if ((threadIdx.x & 31) == 0) red[threadIdx.x >> 5] = ss;
    __syncthreads();
    if (threadIdx.x == 0) {
        float t = 0.f;
#pragma unroll
        for (int i = 0; i < 8; i++) t += red[i];
        red[0] = t;
    }
    __syncthreads();
    const float r = rsqrtf(red[0] / 512.f + 1e-6f);
    for (int i = threadIdx.x; i < 512; i += 256)
        kvn[(size_t)row * 512 + i] = w[i] * (xr[i] * r);

    if (threadIdx.x < 32) {
        const int j = threadIdx.x;
        const int pos = row & (S_ - 1);
        float c = ct[pos * 64 + j], s = st[pos * 64 + j];
        float x1 = xr[512 + j], x2 = xr[544 + j];
        kpe[(size_t)row * 64 + j]      = x1 * c - x2 * s;
        kpe[(size_t)row * 64 + 32 + j] = x2 * c + x1 * s;
    }
}

// ---------------- rope on q_pe slice of each head (in-place) ----------------
__global__ void __launch_bounds__(256) ropeq_k(float* __restrict__ q,
                                               const float* __restrict__ ct,
                                               const float* __restrict__ st)
{
    const int idx = blockIdx.x * 256 + threadIdx.x;
    const int row = idx >> 9;
    const int h = (idx >> 5) & 15;
    const int j = idx & 31;
    const int pos = row & (S_ - 1);
    float* p = q + (size_t)row * 3072 + h * 192 + 128;
    float c = ct[pos * 64 + j], s = st[pos * 64 + j];
    float x1 = p[j], x2 = p[j + 32];
    p[j]      = x1 * c - x2 * s;
    p[j + 32] = x2 * c + x1 * s;
}

// ---------------- flash attention (absorbed MLA) on tensor cores ------------
// qk-dim 192 (128 k_abs + 64 k_pe), v-dim 128; tf32 mma m16n8k8, fp32 softmax.
// K-permuted smem layouts -> LDS.64 fragment feeds, conflict-free
// (strides 200 and 72 are ==8 mod 32).
__global__ void __launch_bounds__(256) attn_k(
    const float* __restrict__ Q,    // [4096, 3072]
    const float* __restrict__ KV,   // [32][2048][256]: k_abs | v_abs
    const float* __restrict__ Kpe,  // [4096, 64]
    const int*   __restrict__ msk,  // [2, 2048]
    float* __restrict__ Out)        // [4096, 2048]
{
    const int qb = blockIdx.x, h = blockIdx.y, b = blockIdx.z;
    const int tid = threadIdx.x;
    const int warp = tid >> 5, lane = tid & 31;
    const int wm = warp >> 1, wn = warp & 1;
    const int g = lane >> 2, tg = lane & 3;

    extern __shared__ uint32_t smu[];
    uint32_t* sQ  = smu;                 // [64][200] tf32, k-permuted cols
    uint32_t* sK  = sQ + 64 * 200;       // [64][200]
    uint32_t* sVT = sK + 64 * 200;       // [128][72] (V transposed, k-permuted rows)
    uint32_t* sP  = sVT + 128 * 72;      // [64][72]
    float* sM = (float*)(sP + 64 * 72);  // [2][64]
    float* sS = sM + 128;                // [2][64]

    const int s0 = qb * 64;
    const float* Qb = Q + (size_t)(b * 2048 + s0) * 3072 + h * 192;
    for (int idx = tid; idx < 64 * 48; idx += 256) {
        int r = idx / 48, c4 = idx % 48;
        float4 v = *reinterpret_cast<const float4*>(Qb + (size_t)r * 3072 + c4 * 4);
        int c = c4 * 4;
        uint32_t* d = sQ + r * 200 + (c & ~7) + ((c >> 2) & 1);
        d[0] = f2tf(v.x); d[2] = f2tf(v.y); d[4] = f2tf(v.z); d[6] = f2tf(v.w);
    }

    const float scale = 0.07216878364870322f;  // 1/sqrt(192)
    const int r1 = wm * 16 + g, r2 = r1 + 8;
    const int sg1 = s0 + r1, sg2 = s0 + r2;
    // permuted positions of within-8 k-indices 2tg and 2tg+1 (for P store)
    const int pos0 = ((2 * tg) & 3) * 2 + (tg >> 1);
    const int pos1 = ((2 * tg + 1) & 3) * 2 + (tg >> 1);

    float m1 = -3.0e38f, m2 = -3.0e38f, l1 = 0.f, l2 = 0.f;
    float o[8][4];
#pragma unroll
    for (int nt = 0; nt < 8; nt++)
#pragma unroll
        for (int r = 0; r < 4; r++) o[nt][r] = 0.f;

    const int* mrow = msk + (size_t)b * 2048;

    for (int kt = 0; kt <= qb; kt++) {
        __syncthreads();
        const float* KVb = KV + ((size_t)(b * 16 + h) * 2048 + kt * 64) * 256;
        for (int idx = tid; idx < 64 * 64; idx += 256) {
            int r = idx >> 6, c4 = idx & 63;
            float4 v = *reinterpret_cast<const float4*>(KVb + (size_t)r * 256 + c4 * 4);
            if (c4 < 32) {
                int c = c4 * 4;
                uint32_t* d = sK + r * 200 + (c & ~7) + ((c >> 2) & 1);
                d[0] = f2tf(v.x); d[2] = f2tf(v.y); d[4] = f2tf(v.z); d[6] = f2tf(v.w);
            } else {
                int vc = (c4 - 32) * 4;
                int pr = (r & ~7) | (((r & 3) << 1) | ((r >> 2) & 1));
                sVT[(vc + 0) * 72 + pr] = f2tf(v.x);
                sVT[(vc + 1) * 72 + pr] = f2tf(v.y);
                sVT[(vc + 2) * 72 + pr] = f2tf(v.z);
                sVT[(vc + 3) * 72 + pr] = f2tf(v.w);
            }
        }
        const float* Kpb = Kpe + (size_t)(b * 2048 + kt * 64) * 64;
        for (int idx = tid; idx < 64 * 16; idx += 256) {
            int r = idx >> 4, c4 = idx & 15;
            float4 v = *reinterpret_cast<const float4*>(Kpb + (size_t)r * 64 + c4 * 4);
            int c = 128 + c4 * 4;
            uint32_t* d = sK + r * 200 + (c & ~7) + ((c >> 2) & 1);
            d[0] = f2tf(v.x); d[2] = f2tf(v.y); d[4] = f2tf(v.z); d[6] = f2tf(v.w);
        }
        __syncthreads();

        // ---- scores: 16x32 per warp over 192-dim contraction ----
        float sc[4][4];
#pragma unroll
        for (int nt = 0; nt < 4; nt++)
#pragma unroll
            for (int r = 0; r < 4; r++) sc[nt][r] = 0.f;

#pragma unroll
        for (int ks = 0; ks < 24; ks++) {
            const int kb8 = ks * 8 + 2 * tg;
            uint2 lo = *reinterpret_cast<const uint2*>(sQ + r1 * 200 + kb8);
            uint2 hi = *reinterpret_cast<const uint2*>(sQ + r2 * 200 + kb8);
#pragma unroll
            for (int nt = 0; nt < 4; nt++) {
                uint2 bb = *reinterpret_cast<const uint2*>(sK + (wn * 32 + nt * 8 + g) * 200 + kb8);
                MMA_TF32(sc[nt], lo.x, hi.x, lo.y, hi.y, bb.x, bb.y);
            }
        }

        // ---- scale + mask + row max ----
        const bool diag = (kt == qb);
        float tm1 = -3.0e38f, tm2 = -3.0e38f;
#pragma unroll
        for (int nt = 0; nt < 4; nt++) {
            int t0 = kt * 64 + wn * 32 + nt * 8 + 2 * tg, t1 = t0 + 1;
            int mv0 = mrow[t0], mv1 = mrow[t1];
            float v0 = sc[nt][0] * scale; if ((diag && t0 > sg1) || mv0 == 0) v0 = -1e15f;
            float v1 = sc[nt][1] * scale; if ((diag && t1 > sg1) || mv1 == 0) v1 = -1e15f;
            float v2 = sc[nt][2] * scale; if ((diag && t0 > sg2) || mv0 == 0) v2 = -1e15f;
            float v3 = sc[nt][3] * scale; if ((diag && t1 > sg2) || mv1 == 0) v3 = -1e15f;
            sc[nt][0] = v0; sc[nt][1] = v1; sc[nt][2] = v2; sc[nt][3] = v3;
            tm1 = fmaxf(tm1, fmaxf(v0, v1));
            tm2 = fmaxf(tm2, fmaxf(v2, v3));
        }
        tm1 = fmaxf(tm1, __shfl_xor_sync(0xffffffffu, tm1, 1));
        tm1 = fmaxf(tm1, __shfl_xor_sync(0xffffffffu, tm1, 2));
        tm2 = fmaxf(tm2, __shfl_xor_sync(0xffffffffu, tm2, 1));
        tm2 = fmaxf(tm2, __shfl_xor_sync(0xffffffffu, tm2, 2));
        if (tg == 0) { sM[wn * 64 + r1] = tm1; sM[wn * 64 + r2] = tm2; }
        __syncthreads();

        float nm1 = fmaxf(m1, fmaxf(sM[r1], sM[64 + r1]));
        float nm2 = fmaxf(m2, fmaxf(sM[r2], sM[64 + r2]));
        float al1 = expf(m1 - nm1), al2 = expf(m2 - nm2);
        m1 = nm1; m2 = nm2;

        // ---- exp + P store (tf32, k-permuted) + row sum ----
        float ls1 = 0.f, ls2 = 0.f;
#pragma unroll
        for (int nt = 0; nt < 4; nt++) {
            float p0 = expf(sc[nt][0] - nm1);
            float p1 = expf(sc[nt][1] - nm1);
            float p2 = expf(sc[nt][2] - nm2);
            float p3 = expf(sc[nt][3] - nm2);
            ls1 += p0 + p1; ls2 += p2 + p3;
            int base = wn * 32 + nt * 8;
            sP[r1 * 72 + base + pos0] = f2tf(p0);
            sP[r1 * 72 + base + pos1] = f2tf(p1);
            sP[r2 * 72 + base + pos0] = f2tf(p2);
            sP[r2 * 72 + base + pos1] = f2tf(p3);
        }
        ls1 += __shfl_xor_sync(0xffffffffu, ls1, 1);
        ls1 += __shfl_xor_sync(0xffffffffu, ls1, 2);
        ls2 += __shfl_xor_sync(0xffffffffu, ls2, 1);
        ls2 += __shfl_xor_sync(0xffffffffu, ls2, 2);
        if (tg == 0) { sS[wn * 64 + r1] = ls1; sS[wn * 64 + r2] = ls2; }
        __syncthreads();

        l1 = l1 * al1 + sS[r1] + sS[64 + r1];
        l2 = l2 * al2 + sS[r2] + sS[64 + r2];

        // ---- O rescale + PV: 16x64 per warp over 64-dim contraction ----
#pragma unroll
        for (int nt = 0; nt < 8; nt++) {
            o[nt][0] *= al1; o[nt][1] *= al1; o[nt][2] *= al2; o[nt][3] *= al2;
        }
#pragma unroll
        for (int ks = 0; ks < 8; ks++) {
            const int kb8 = ks * 8 + 2 * tg;
            uint2 lo = *reinterpret_cast<const uint2*>(sP + r1 * 72 + kb8);
            uint2 hi = *reinterpret_cast<const uint2*>(sP + r2 * 72 + kb8);
#pragma unroll
            for (int nt = 0; nt < 8; nt++) {
                uint2 bb = *reinterpret_cast<const uint2*>(sVT + (wn * 64 + nt * 8 + g) * 72 + kb8);
                MMA_TF32(o[nt], lo.x, hi.x, lo.y, hi.y, bb.x, bb.y);
            }
        }
    }

    // ---- epilogue ----
    const float i1 = 1.f / l1, i2 = 1.f / l2;
    float* orow1 = Out + (size_t)(b * 2048 + sg1) * 2048 + h * 128;
    float* orow2 = Out + (size_t)(b * 2048 + sg2) * 2048 + h * 128;
#pragma unroll
    for (int nt = 0; nt < 8; nt++) {
        int c = wn * 64 + nt * 8 + 2 * tg;
        *reinterpret_cast<float2*>(orow1 + c) = make_float2(o[nt][0] * i1, o[nt][1] * i1);
        *reinterpret_cast<float2*>(orow2 + c) = make_float2(o[nt][2] * i2, o[nt][3] * i2);
    }
}

// ------------------------------- host side ---------------------------------
extern "C" void kernel_launch(void* const* d_in, const int* in_sizes, int n_in,
                              void* d_out, int out_size)
{
    (void)in_sizes; (void)n_in; (void)out_size;
    const float* x        = (const float*)d_in[0];
    const int*   mask     = (const int*)  d_in[1];
    const float* wq_a_w   = (const float*)d_in[2];
    const float* wq_a_b   = (const float*)d_in[3];
    const float* q_norm_w = (const float*)d_in[4];
    const float* wq_b_w   = (const float*)d_in[5];
    const float* wq_b_b   = (const float*)d_in[6];
    const float* wkv_a_w  = (const float*)d_in[7];
    const float* wkv_a_b  = (const float*)d_in[8];
    const float* kv_norm_w= (const float*)d_in[9];
    const float* wkv_b_w  = (const float*)d_in[10];
    const float* wo_w     = (const float*)d_in[11];
    const float* wo_b     = (const float*)d_in[12];
    float* out = (float*)d_out;

    float *qa, *q, *kvf, *kvn, *kpe, *kvab, *att, *ct, *st;
    cudaGetSymbolAddress((void**)&qa,   g_qa);
    cudaGetSymbolAddress((void**)&q,    g_q);
    cudaGetSymbolAddress((void**)&kvf,  g_kvf);
    cudaGetSymbolAddress((void**)&kvn,  g_kvn);
    cudaGetSymbolAddress((void**)&kpe,  g_kpe);
    cudaGetSymbolAddress((void**)&kvab, g_kvab);
    cudaGetSymbolAddress((void**)&att,  g_att);
    cudaGetSymbolAddress((void**)&ct,   g_cos);
    cudaGetSymbolAddress((void**)&st,   g_sin);

    rope_tab_k<<<S_, 32>>>(ct, st);

    // q_a = x @ wq_a^T + b   [4096,2048]x[1536,2048]
    { dim3 g(QL_ / 128, ROWS_ / 128, 1);
      sgemm_bias<<<g, 256>>>(x, wq_a_w, wq_a_b, qa, ROWS_, QL_, H_, 1, 0, 1, 0, 0); }
    rmsnorm_k<<<ROWS_, 256>>>(qa, q_norm_w, QL_);
    // q = q_a @ wq_b^T + b   [4096,1536]x[3072,1536]
    { dim3 g((NH_ * QKH_) / 128, ROWS_ / 128, 1);
      sgemm_bias<<<g, 256>>>(qa, wq_b_w, wq_b_b, q, ROWS_, NH_ * QKH_, QL_, 1, 0, 1, 0, 0); }
    // kv_full = x @ wkv_a^T + b   [4096,2048]x[576,2048]
    { dim3 g((KVL_ + ROPE_ + 127) / 128, ROWS_ / 128, 1);
      sgemm_bias<<<g, 256>>>(x, wkv_a_w, wkv_a_b, kvf, ROWS_, KVL_ + ROPE_, H_, 1, 0, 1, 0, 0); }
    kvprep_k<<<ROWS_, 256>>>(kvf, kv_norm_w, kvn, kpe, ct, st);
    ropeq_k<<<(ROWS_ * NH_ * 32) / 256, 256>>>(q, ct, st);

    // absorbed K/V: per (b,h): kvab[z] = kvn[b] (2048x512) @ wkv_b[h] (256x512)^T
    { dim3 g(256 / 128, S_ / 128, B_ * NH_);
      sgemm_bias<<<g, 256>>>(kvn, wkv_b_w, nullptr, kvab, S_, 256, KVL_,
                             NH_, (long long)S_ * KVL_,
                             NH_, 256LL * KVL_,
                             (long long)S_ * 256); }

    // flash attention (tensor-core, LDS.64 frag feeds)
    const int attn_smem = (64 * 200 * 2 + 128 * 72 + 64 * 72 + 256) * 4;  // 158,720 B
    cudaFuncSetAttribute(attn_k, cudaFuncAttributeMaxDynamicSharedMemorySize, attn_smem);
    attn_k<<<dim3(S_ / 64, NH_, B_), 256, attn_smem>>>(q, kvab, kpe, mask, att);

    // out = att @ wo^T + b   [4096,2048]x[2048,2048]
    { dim3 g(H_ / 128, ROWS_ / 128, 1);
      sgemm_bias<<<g, 256>>>(att, wo_w, wo_b, out, ROWS_, H_, NH_ * VD_, 1, 0, 1, 0, 0); }
}

// round 12
// speedup vs baseline: 1.1651x; 1.1571x over previous
#include <cuda_runtime.h>
#include <math.h>
#include <stddef.h>
#include <stdint.h>

// MLA shapes (compile-time constants)
#define B_    2
#define S_    2048
#define H_    2048
#define NH_   16
#define QL_   1536
#define KVL_  512
#define NOPE_ 128
#define ROPE_ 64
#define VD_   128
#define QKH_  192
#define ROWS_ (B_*S_)   // 4096

// ---------------- scratch (device globals: no allocs allowed) ----------------
__device__ float g_qa  [(size_t)ROWS_*QL_];
__device__ float g_q   [(size_t)ROWS_*NH_*QKH_];
__device__ float g_kvf [(size_t)ROWS_*(KVL_+ROPE_)];
__device__ float g_kvn [(size_t)ROWS_*KVL_];
__device__ float g_kpe [(size_t)ROWS_*ROPE_];
__device__ float g_kvab[(size_t)B_*NH_*S_*256];
__device__ float g_att [(size_t)ROWS_*NH_*VD_];
__device__ float g_cos [(size_t)S_*ROPE_];
__device__ float g_sin [(size_t)S_*ROPE_];

// ---------------- tf32 helpers ----------------
__device__ __forceinline__ uint32_t f2tf(float x) {
    uint32_t r;
    asm("cvt.rna.tf32.f32 %0, %1;" : "=r"(r) : "f"(x));
    return r;
}

#define MMA_TF32(d, a0, a1, a2, a3, b0, b1)                                  \
    asm volatile(                                                            \
        "mma.sync.aligned.m16n8k8.row.col.f32.tf32.tf32.f32 "                \
        "{%0,%1,%2,%3}, {%4,%5,%6,%7}, {%8,%9}, {%0,%1,%2,%3};"              \
        : "+f"((d)[0]), "+f"((d)[1]), "+f"((d)[2]), "+f"((d)[3])             \
        : "r"(a0), "r"(a1), "r"(a2), "r"(a3), "r"(b0), "r"(b1))

#define CP_ASYNC16(dst, src) \
    asm volatile("cp.async.ca.shared.global [%0], [%1], 16;" :: "r"(dst), "l"(src))
#define CP_COMMIT()  asm volatile("cp.async.commit_group;")
#define CP_WAIT1()   asm volatile("cp.async.wait_group 1;")
#define CP_WAIT0()   asm volatile("cp.async.wait_group 0;")

// ---------------- tensor-core GEMM: C = A(MxK) @ W(NxK)^T + bias ------------
// tf32 mma.sync m16n8k8, fp32 accumulate. 128x128 tile, BK=32, 256 threads,
// 8 warps 2x4, warp tile 64x32 (4x4 m16n8 tiles).
// cp.async 2-stage pipeline: fp32 staged raw (no registers live across the
// MMA block), tf32 convert on the fragment-load side (bit-identical values).
// Smem row stride 36 (==4 mod 32) -> fragment LDS addresses 4g+tg hit all
// 32 banks; staging writes are contiguous 16B rows -> conflict-free both ways.
__global__ void __launch_bounds__(256, 2) sgemm_bias(
    const float* __restrict__ A, const float* __restrict__ W,
    const float* __restrict__ bias, float* __restrict__ C,
    int M, int N, int K,
    int zdA, long long sA, int zmB, long long sB, long long sC)
{
    extern __shared__ float sg[];   // 2 stages x (A 128*36 + B 128*36) fp32

    const int z = blockIdx.z;
    A += (long long)(z / zdA) * sA;
    W += (long long)(z % zmB) * sB;
    C += (long long)z * sC;

    const int tid  = threadIdx.x;
    const int warp = tid >> 5, lane = tid & 31;
    const int wm = warp >> 2;
    const int wn = warp & 3;
    const int g  = lane >> 2;
    const int tg = lane & 3;
    const int m0 = blockIdx.y * 128;
    const int n0 = blockIdx.x * 128;

    float acc[4][4][4];
#pragma unroll
    for (int mt = 0; mt < 4; mt++)
#pragma unroll
        for (int nt = 0; nt < 4; nt++)
#pragma unroll
            for (int r = 0; r < 4; r++) acc[mt][nt][r] = 0.f;

    // stage tile k0 into buffer s via cp.async (raw fp32)
    auto stage = [&](int k0, int s) {
        float* Ab = sg + s * 9216;
        float* Bb = Ab + 4608;
#pragma unroll
        for (int it = 0; it < 4; it++) {
            int idx = tid + it * 256;
            int r = idx >> 3;
            int c = (idx & 7) << 2;
            uint32_t da = (uint32_t)__cvta_generic_to_shared(Ab + r * 36 + c);
            CP_ASYNC16(da, A + (size_t)(m0 + r) * K + k0 + c);
            int n = n0 + r;
            if (n < N) {
                uint32_t db = (uint32_t)__cvta_generic_to_shared(Bb + r * 36 + c);
                CP_ASYNC16(db, W + (size_t)n * K + k0 + c);
            } else {
                *reinterpret_cast<float4*>(Bb + r * 36 + c) = make_float4(0.f, 0.f, 0.f, 0.f);
            }
        }
        CP_COMMIT();
    };

    const int nk = K >> 5;
    stage(0, 0);

    for (int kb = 0; kb < nk; kb++) {
        if (kb + 1 < nk) { stage((kb + 1) << 5, (kb + 1) & 1); CP_WAIT1(); }
        else             { CP_WAIT0(); }
        __syncthreads();

        const float* Ab = sg + (kb & 1) * 9216;
        const float* Bb = Ab + 4608;
#pragma unroll
        for (int ks = 0; ks < 4; ks++) {
            const int kc = ks * 8 + tg;
            uint32_t af[4][4], bf[4][2];
#pragma unroll
            for (int mt = 0; mt < 4; mt++) {
                int rb = wm * 64 + mt * 16 + g;
                af[mt][0] = f2tf(Ab[rb * 36 + kc]);
                af[mt][1] = f2tf(Ab[(rb + 8) * 36 + kc]);
                af[mt][2] = f2tf(Ab[rb * 36 + kc + 4]);
                af[mt][3] = f2tf(Ab[(rb + 8) * 36 + kc + 4]);
            }
#pragma unroll
            for (int nt = 0; nt < 4; nt++) {
                int nb = wn * 32 + nt * 8 + g;
                bf[nt][0] = f2tf(Bb[nb * 36 + kc]);
                bf[nt][1] = f2tf(Bb[nb * 36 + kc + 4]);
            }
#pragma unroll
            for (int mt = 0; mt < 4; mt++)
#pragma unroll
                for (int nt = 0; nt < 4; nt++)
                    MMA_TF32(acc[mt][nt], af[mt][0], af[mt][1], af[mt][2], af[mt][3],
                             bf[nt][0], bf[nt][1]);
        }
        __syncthreads();
    }

#pragma unroll
    for (int mt = 0; mt < 4; mt++) {
        int row = m0 + wm * 64 + mt * 16 + g;
#pragma unroll
        for (int nt = 0; nt < 4; nt++) {
            int col = n0 + wn * 32 + nt * 8 + (tg << 1);
            if (col < N) {
                float2 bv = make_float2(0.f, 0.f);
                if (bias) bv = *reinterpret_cast<const float2*>(bias + col);
                float2 v0 = make_float2(acc[mt][nt][0] + bv.x, acc[mt][nt][1] + bv.y);
                float2 v1 = make_float2(acc[mt][nt][2] + bv.x, acc[mt][nt][3] + bv.y);
                *reinterpret_cast<float2*>(C + (size_t)row * N + col) = v0;
                *reinterpret_cast<float2*>(C + (size_t)(row + 8) * N + col) = v1;
            }
        }
    }
}

// ---------------- RMSNorm (in-place), one block per row --------------------
__global__ void __launch_bounds__(256) rmsnorm_k(float* __restrict__ x,
                                                 const float* __restrict__ w, int D)
{
    const int row = blockIdx.x;
    float* xr = x + (size_t)row * D;
    float ss = 0.f;
    for (int i = threadIdx.x; i < D; i += 256) { float v = xr[i]; ss = fmaf(v, v, ss); }
    __shared__ float red[8];
#pragma unroll
    for (int d = 16; d; d >>= 1) ss += __shfl_xor_sync(0xffffffffu, ss, d);
    if ((threadIdx.x & 31) == 0) red[threadIdx.x >> 5] = ss;
    __syncthreads();
    if (threadIdx.x == 0) {
        float t = 0.f;
#pragma unroll
        for (int i = 0; i < 8; i++) t += red[i];
        red[0] = t;
    }
    __syncthreads();
    const float r = rsqrtf(red[0] / (float)D + 1e-6f);
    for (int i = threadIdx.x; i < D; i += 256) xr[i] = w[i] * (xr[i] * r);
}

// ---------------- RoPE tables (fp64 trig for range safety) ------------------
__global__ void rope_tab_k(float* __restrict__ ct, float* __restrict__ st)
{
    const int pos = blockIdx.x;
    const int j = threadIdx.x;
    double inv = pow(10000.0, -((double)j) / 32.0);
    float ang = (float)pos * (float)inv;
    float c = (float)cos((double)ang);
    float s = (float)sin((double)ang);
    ct[pos * 64 + j] = c; ct[pos * 64 + j + 32] = c;
    st[pos * 64 + j] = s; st[pos * 64 + j + 32] = s;
}

// ---------------- kv split: rmsnorm first 512, rope last 64 -----------------
__global__ void __launch_bounds__(256) kvprep_k(
    const float* __restrict__ kvf, const float* __restrict__ w,
    float* __restrict__ kvn, float* __restrict__ kpe,
    const float* __restrict__ ct, const float* __restrict__ st)
{
    const int row = blockIdx.x;
    const float* xr = kvf + (size_t)row * 576;
    float ss = 0.f;
    for (int i = threadIdx.x; i < 512; i += 256) { float v = xr[i]; ss = fmaf(v, v, ss); }
    __shared__ float red[8];
#pragma unroll
    for (int d = 16; d; d >>= 1) ss += __shfl_xor_sync(0xffffffffu, ss, d);
    if ((threadIdx.x & 31) == 0) red[threadIdx.x >> 5] = ss;
    __syncthreads();
    if (threadIdx.x == 0) {
        float t = 0.f;
#pragma unroll
        for (int i = 0; i < 8; i++) t += red[i];
        red[0] = t;
    }
    __syncthreads();
    const float r = rsqrtf(red[0] / 512.f + 1e-6f);
    for (int i = threadIdx.x; i < 512; i += 256)
        kvn[(size_t)row * 512 + i] = w[i] * (xr[i] * r);

    if (threadIdx.x < 32) {
        const int j = threadIdx.x;
        const int pos = row & (S_ - 1);
        float c = ct[pos * 64 + j], s = st[pos * 64 + j];
        float x1 = xr[512 + j], x2 = xr[544 + j];
        kpe[(size_t)row * 64 + j]      = x1 * c - x2 * s;
        kpe[(size_t)row * 64 + 32 + j] = x2 * c + x1 * s;
    }
}

// ---------------- rope on q_pe slice of each head (in-place) ----------------
__global__ void __launch_bounds__(256) ropeq_k(float* __restrict__ q,
                                               const float* __restrict__ ct,
                                               const float* __restrict__ st)
{
    const int idx = blockIdx.x * 256 + threadIdx.x;
    const int row = idx >> 9;
    const int h = (idx >> 5) & 15;
    const int j = idx & 31;
    const int pos = row & (S_ - 1);
    float* p = q + (size_t)row * 3072 + h * 192 + 128;
    float c = ct[pos * 64 + j], s = st[pos * 64 + j];
    float x1 = p[j], x2 = p[j + 32];
    p[j]      = x1 * c - x2 * s;
    p[j + 32] = x2 * c + x1 * s;
}

// ---------------- flash attention (absorbed MLA) on tensor cores ------------
// Round-9 proven version: qk-dim 192, v-dim 128; tf32 mma m16n8k8, fp32
// softmax; scalar LDS fragment feeds (strides 196/68 are ==4 mod 32).
__global__ void __launch_bounds__(256) attn_k(
    const float* __restrict__ Q,    // [4096, 3072]
    const float* __restrict__ KV,   // [32][2048][256]: k_abs | v_abs
    const float* __restrict__ Kpe,  // [4096, 64]
    const int*   __restrict__ msk,  // [2, 2048]
    float* __restrict__ Out)        // [4096, 2048]
{
    const int qb = blockIdx.x, h = blockIdx.y, b = blockIdx.z;
    const int tid = threadIdx.x;
    const int warp = tid >> 5, lane = tid & 31;
    const int wm = warp >> 1, wn = warp & 1;
    const int g = lane >> 2, tg = lane & 3;

    extern __shared__ uint32_t smu[];
    uint32_t* sQ  = smu;                 // [64][196] tf32
    uint32_t* sK  = sQ + 64 * 196;       // [64][196]
    uint32_t* sVT = sK + 64 * 196;       // [128][68] (V transposed)
    uint32_t* sP  = sVT + 128 * 68;      // [64][68]
    float* sM = (float*)(sP + 64 * 68);  // [2][64]
    float* sS = sM + 128;                // [2][64]

    const int s0 = qb * 64;
    const float* Qb = Q + (size_t)(b * 2048 + s0) * 3072 + h * 192;
    for (int idx = tid; idx < 64 * 48; idx += 256) {
        int r = idx / 48, c4 = idx % 48;
        float4 v = *reinterpret_cast<const float4*>(Qb + (size_t)r * 3072 + c4 * 4);
        uint32_t* d = sQ + r * 196 + c4 * 4;
        d[0] = f2tf(v.x); d[1] = f2tf(v.y); d[2] = f2tf(v.z); d[3] = f2tf(v.w);
    }

    const float scale = 0.07216878364870322f;  // 1/sqrt(192)
    const int r1 = wm * 16 + g, r2 = r1 + 8;
    const int sg1 = s0 + r1, sg2 = s0 + r2;

    float m1 = -3.0e38f, m2 = -3.0e38f, l1 = 0.f, l2 = 0.f;
    float o[8][4];
#pragma unroll
    for (int nt = 0; nt < 8; nt++)
#pragma unroll
        for (int r = 0; r < 4; r++) o[nt][r] = 0.f;

    const int* mrow = msk + (size_t)b * 2048;

    for (int kt = 0; kt <= qb; kt++) {
        __syncthreads();
        const float* KVb = KV + ((size_t)(b * 16 + h) * 2048 + kt * 64) * 256;
        for (int idx = tid; idx < 64 * 64; idx += 256) {
            int r = idx >> 6, c4 = idx & 63;
            float4 v = *reinterpret_cast<const float4*>(KVb + (size_t)r * 256 + c4 * 4);
            if (c4 < 32) {
                uint32_t* d = sK + r * 196 + c4 * 4;
                d[0] = f2tf(v.x); d[1] = f2tf(v.y); d[2] = f2tf(v.z); d[3] = f2tf(v.w);
            } else {
                int vc = (c4 - 32) * 4;
                sVT[(vc + 0) * 68 + r] = f2tf(v.x);
                sVT[(vc + 1) * 68 + r] = f2tf(v.y);
                sVT[(vc + 2) * 68 + r] = f2tf(v.z);
                sVT[(vc + 3) * 68 + r] = f2tf(v.w);
            }
        }
        const float* Kpb = Kpe + (size_t)(b * 2048 + kt * 64) * 64;
        for (int idx = tid; idx < 64 * 16; idx += 256) {
            int r = idx >> 4, c4 = idx & 15;
            float4 v = *reinterpret_cast<const float4*>(Kpb + (size_t)r * 64 + c4 * 4);
            uint32_t* d = sK + r * 196 + 128 + c4 * 4;
            d[0] = f2tf(v.x); d[1] = f2tf(v.y); d[2] = f2tf(v.z); d[3] = f2tf(v.w);
        }
        __syncthreads();

        // ---- scores: 16x32 per warp over 192-dim contraction ----
        float sc[4][4];
#pragma unroll
        for (int nt = 0; nt < 4; nt++)
#pragma unroll
            for (int r = 0; r < 4; r++) sc[nt][r] = 0.f;

#pragma unroll
        for (int ks = 0; ks < 24; ks++) {
            const int kc = ks * 8 + tg;
            const uint32_t* aq = sQ + r1 * 196 + kc;
            uint32_t a0 = aq[0], a1 = aq[8 * 196], a2 = aq[4], a3 = aq[8 * 196 + 4];
#pragma unroll
            for (int nt = 0; nt < 4; nt++) {
                const uint32_t* bk = sK + (wn * 32 + nt * 8 + g) * 196 + kc;
                MMA_TF32(sc[nt], a0, a1, a2, a3, bk[0], bk[4]);
            }
        }

        // ---- scale + mask + row max ----
        const bool diag = (kt == qb);
        float tm1 = -3.0e38f, tm2 = -3.0e38f;
#pragma unroll
        for (int nt = 0; nt < 4; nt++) {
            int t0 = kt * 64 + wn * 32 + nt * 8 + 2 * tg, t1 = t0 + 1;
            int mv0 = mrow[t0], mv1 = mrow[t1];
            float v0 = sc[nt][0] * scale; if ((diag && t0 > sg1) || mv0 == 0) v0 = -1e15f;
            float v1 = sc[nt][1] * scale; if ((diag && t1 > sg1) || mv1 == 0) v1 = -1e15f;
            float v2 = sc[nt][2] * scale; if ((diag && t0 > sg2) || mv0 == 0) v2 = -1e15f;
            float v3 = sc[nt][3] * scale; if ((diag && t1 > sg2) || mv1 == 0) v3 = -1e15f;
            sc[nt][0] = v0; sc[nt][1] = v1; sc[nt][2] = v2; sc[nt][3] = v3;
            tm1 = fmaxf(tm1, fmaxf(v0, v1));
            tm2 = fmaxf(tm2, fmaxf(v2, v3));
        }
        tm1 = fmaxf(tm1, __shfl_xor_sync(0xffffffffu, tm1, 1));
        tm1 = fmaxf(tm1, __shfl_xor_sync(0xffffffffu, tm1, 2));
        tm2 = fmaxf(tm2, __shfl_xor_sync(0xffffffffu, tm2, 1));
        tm2 = fmaxf(tm2, __shfl_xor_sync(0xffffffffu, tm2, 2));
        if (tg == 0) { sM[wn * 64 + r1] = tm1; sM[wn * 64 + r2] = tm2; }
        __syncthreads();

        float nm1 = fmaxf(m1, fmaxf(sM[r1], sM[64 + r1]));
        float nm2 = fmaxf(m2, fmaxf(sM[r2], sM[64 + r2]));
        float al1 = expf(m1 - nm1), al2 = expf(m2 - nm2);
        m1 = nm1; m2 = nm2;

        // ---- exp + P store (tf32) + row sum ----
        float ls1 = 0.f, ls2 = 0.f;
#pragma unroll
        for (int nt = 0; nt < 4; nt++) {
            float p0 = expf(sc[nt][0] - nm1);
            float p1 = expf(sc[nt][1] - nm1);
            float p2 = expf(sc[nt][2] - nm2);
            float p3 = expf(sc[nt][3] - nm2);
            ls1 += p0 + p1; ls2 += p2 + p3;
            int jc = wn * 32 + nt * 8 + 2 * tg;
            sP[r1 * 68 + jc]     = f2tf(p0);
            sP[r1 * 68 + jc + 1] = f2tf(p1);
            sP[r2 * 68 + jc]     = f2tf(p2);
            sP[r2 * 68 + jc + 1] = f2tf(p3);
        }
        ls1 += __shfl_xor_sync(0xffffffffu, ls1, 1);
        ls1 += __shfl_xor_sync(0xffffffffu, ls1, 2);
        ls2 += __shfl_xor_sync(0xffffffffu, ls2, 1);
        ls2 += __shfl_xor_sync(0xffffffffu, ls2, 2);
        if (tg == 0) { sS[wn * 64 + r1] = ls1; sS[wn * 64 + r2] = ls2; }
        __syncthreads();

        l1 = l1 * al1 + sS[r1] + sS[64 + r1];
        l2 = l2 * al2 + sS[r2] + sS[64 + r2];

        // ---- O rescale + PV: 16x64 per warp over 64-dim contraction ----
#pragma unroll
        for (int nt = 0; nt < 8; nt++) {
            o[nt][0] *= al1; o[nt][1] *= al1; o[nt][2] *= al2; o[nt][3] *= al2;
        }
#pragma unroll
        for (int ks = 0; ks < 8; ks++) {
            const int kc = ks * 8 + tg;
            const uint32_t* ap = sP + r1 * 68 + kc;
            uint32_t a0 = ap[0], a1 = ap[8 * 68], a2 = ap[4], a3 = ap[8 * 68 + 4];
#pragma unroll
            for (int nt = 0; nt < 8; nt++) {
                const uint32_t* bv = sVT + (wn * 64 + nt * 8 + g) * 68 + kc;
                MMA_TF32(o[nt], a0, a1, a2, a3, bv[0], bv[4]);
            }
        }
    }

    // ---- epilogue ----
    const float i1 = 1.f / l1, i2 = 1.f / l2;
    float* orow1 = Out + (size_t)(b * 2048 + sg1) * 2048 + h * 128;
    float* orow2 = Out + (size_t)(b * 2048 + sg2) * 2048 + h * 128;
#pragma unroll
    for (int nt = 0; nt < 8; nt++) {
        int c = wn * 64 + nt * 8 + 2 * tg;
        *reinterpret_cast<float2*>(orow1 + c) = make_float2(o[nt][0] * i1, o[nt][1] * i1);
        *reinterpret_cast<float2*>(orow2 + c) = make_float2(o[nt][2] * i2, o[nt][3] * i2);
    }
}

// ------------------------------- host side ---------------------------------
extern "C" void kernel_launch(void* const* d_in, const int* in_sizes, int n_in,
                              void* d_out, int out_size)
{
    (void)in_sizes; (void)n_in; (void)out_size;
    const float* x        = (const float*)d_in[0];
    const int*   mask     = (const int*)  d_in[1];
    const float* wq_a_w   = (const float*)d_in[2];
    const float* wq_a_b   = (const float*)d_in[3];
    const float* q_norm_w = (const float*)d_in[4];
    const float* wq_b_w   = (const float*)d_in[5];
    const float* wq_b_b   = (const float*)d_in[6];
    const float* wkv_a_w  = (const float*)d_in[7];
    const float* wkv_a_b  = (const float*)d_in[8];
    const float* kv_norm_w= (const float*)d_in[9];
    const float* wkv_b_w  = (const float*)d_in[10];
    const float* wo_w     = (const float*)d_in[11];
    const float* wo_b     = (const float*)d_in[12];
    float* out = (float*)d_out;

    float *qa, *q, *kvf, *kvn, *kpe, *kvab, *att, *ct, *st;
    cudaGetSymbolAddress((void**)&qa,   g_qa);
    cudaGetSymbolAddress((void**)&q,    g_q);
    cudaGetSymbolAddress((void**)&kvf,  g_kvf);
    cudaGetSymbolAddress((void**)&kvn,  g_kvn);
    cudaGetSymbolAddress((void**)&kpe,  g_kpe);
    cudaGetSymbolAddress((void**)&kvab, g_kvab);
    cudaGetSymbolAddress((void**)&att,  g_att);
    cudaGetSymbolAddress((void**)&ct,   g_cos);
    cudaGetSymbolAddress((void**)&st,   g_sin);

    const int gemm_smem = 2 * 9216 * 4;   // 73,728 B (2 fp32 stages)
    cudaFuncSetAttribute(sgemm_bias, cudaFuncAttributeMaxDynamicSharedMemorySize, gemm_smem);

    rope_tab_k<<<S_, 32>>>(ct, st);

    // q_a = x @ wq_a^T + b   [4096,2048]x[1536,2048]
    { dim3 g(QL_ / 128, ROWS_ / 128, 1);
      sgemm_bias<<<g, 256, gemm_smem>>>(x, wq_a_w, wq_a_b, qa, ROWS_, QL_, H_, 1, 0, 1, 0, 0); }
    rmsnorm_k<<<ROWS_, 256>>>(qa, q_norm_w, QL_);
    // q = q_a @ wq_b^T + b   [4096,1536]x[3072,1536]
    { dim3 g((NH_ * QKH_) / 128, ROWS_ / 128, 1);
      sgemm_bias<<<g, 256, gemm_smem>>>(qa, wq_b_w, wq_b_b, q, ROWS_, NH_ * QKH_, QL_, 1, 0, 1, 0, 0); }
    // kv_full = x @ wkv_a^T + b   [4096,2048]x[576,2048]
    { dim3 g((KVL_ + ROPE_ + 127) / 128, ROWS_ / 128, 1);
      sgemm_bias<<<g, 256, gemm_smem>>>(x, wkv_a_w, wkv_a_b, kvf, ROWS_, KVL_ + ROPE_, H_, 1, 0, 1, 0, 0); }
    kvprep_k<<<ROWS_, 256>>>(kvf, kv_norm_w, kvn, kpe, ct, st);
    ropeq_k<<<(ROWS_ * NH_ * 32) / 256, 256>>>(q, ct, st);

    // absorbed K/V: per (b,h): kvab[z] = kvn[b] (2048x512) @ wkv_b[h] (256x512)^T
    { dim3 g(256 / 128, S_ / 128, B_ * NH_);
      sgemm_bias<<<g, 256, gemm_smem>>>(kvn, wkv_b_w, nullptr, kvab, S_, 256, KVL_,
                             NH_, (long long)S_ * KVL_,
                             NH_, 256LL * KVL_,
                             (long long)S_ * 256); }

    // flash attention (tensor-core, round-9 layout)
    const int attn_smem = (64 * 196 * 2 + 128 * 68 + 64 * 68) * 4 + 2 * 128 * 4;  // 153,600 B
    cudaFuncSetAttribute(attn_k, cudaFuncAttributeMaxDynamicSharedMemorySize, attn_smem);
    attn_k<<<dim3(S_ / 64, NH_, B_), 256, attn_smem>>>(q, kvab, kpe, mask, att);

    // out = att @ wo^T + b   [4096,2048]x[2048,2048]
    { dim3 g(H_ / 128, ROWS_ / 128, 1);
      sgemm_bias<<<g, 256, gemm_smem>>>(att, wo_w, wo_b, out, ROWS_, H_, NH_ * VD_, 1, 0, 1, 0, 0); }
}

// round 14
// speedup vs baseline: 1.4021x; 1.2034x over previous
#include <cuda_runtime.h>
#include <math.h>
#include <stddef.h>
#include <stdint.h>

// MLA shapes (compile-time constants)
#define B_    2
#define S_    2048
#define H_    2048
#define NH_   16
#define QL_   1536
#define KVL_  512
#define NOPE_ 128
#define ROPE_ 64
#define VD_   128
#define QKH_  192
#define ROWS_ (B_*S_)   // 4096

// ---------------- scratch (device globals: no allocs allowed) ----------------
__device__ float g_qa  [(size_t)ROWS_*QL_];
__device__ float g_q   [(size_t)ROWS_*NH_*QKH_];
__device__ float g_kvf [(size_t)ROWS_*(KVL_+ROPE_)];
__device__ float g_kvn [(size_t)ROWS_*KVL_];
__device__ float g_kpe [(size_t)ROWS_*ROPE_];
__device__ float g_kvab[(size_t)B_*NH_*S_*256];
__device__ float g_att [(size_t)ROWS_*NH_*VD_];
__device__ float g_cos [(size_t)S_*ROPE_];
__device__ float g_sin [(size_t)S_*ROPE_];

// ---------------- tf32 helpers ----------------
__device__ __forceinline__ uint32_t f2tf(float x) {
    uint32_t r;
    asm("cvt.rna.tf32.f32 %0, %1;" : "=r"(r) : "f"(x));
    return r;
}

#define MMA_TF32(d, a0, a1, a2, a3, b0, b1)                                  \
    asm volatile(                                                            \
        "mma.sync.aligned.m16n8k8.row.col.f32.tf32.tf32.f32 "                \
        "{%0,%1,%2,%3}, {%4,%5,%6,%7}, {%8,%9}, {%0,%1,%2,%3};"              \
        : "+f"((d)[0]), "+f"((d)[1]), "+f"((d)[2]), "+f"((d)[3])             \
        : "r"(a0), "r"(a1), "r"(a2), "r"(a3), "r"(b0), "r"(b1))

#define CP_ASYNC16(dst, src) \
    asm volatile("cp.async.ca.shared.global [%0], [%1], 16;" :: "r"(dst), "l"(src))
#define CP_COMMIT()  asm volatile("cp.async.commit_group;")
#define CP_WAIT1()   asm volatile("cp.async.wait_group 1;")
#define CP_WAIT0()   asm volatile("cp.async.wait_group 0;")

// ---------------- tensor-core GEMM: C = A(MxK) @ W(NxK)^T + bias ------------
// (round-12 proven) tf32 mma m16n8k8, 128x128 tile, BK=32, cp.async 2-stage.
__global__ void __launch_bounds__(256, 2) sgemm_bias(
    const float* __restrict__ A, const float* __restrict__ W,
    const float* __restrict__ bias, float* __restrict__ C,
    int M, int N, int K,
    int zdA, long long sA, int zmB, long long sB, long long sC)
{
    extern __shared__ float sg[];   // 2 stages x (A 128*36 + B 128*36) fp32

    const int z = blockIdx.z;
    A += (long long)(z / zdA) * sA;
    W += (long long)(z % zmB) * sB;
    C += (long long)z * sC;

    const int tid  = threadIdx.x;
    const int warp = tid >> 5, lane = tid & 31;
    const int wm = warp >> 2;
    const int wn = warp & 3;
    const int g  = lane >> 2;
    const int tg = lane & 3;
    const int m0 = blockIdx.y * 128;
    const int n0 = blockIdx.x * 128;

    float acc[4][4][4];
#pragma unroll
    for (int mt = 0; mt < 4; mt++)
#pragma unroll
        for (int nt = 0; nt < 4; nt++)
#pragma unroll
            for (int r = 0; r < 4; r++) acc[mt][nt][r] = 0.f;

    auto stage = [&](int k0, int s) {
        float* Ab = sg + s * 9216;
        float* Bb = Ab + 4608;
#pragma unroll
        for (int it = 0; it < 4; it++) {
            int idx = tid + it * 256;
            int r = idx >> 3;
            int c = (idx & 7) << 2;
            uint32_t da = (uint32_t)__cvta_generic_to_shared(Ab + r * 36 + c);
            CP_ASYNC16(da, A + (size_t)(m0 + r) * K + k0 + c);
            int n = n0 + r;
            if (n < N) {
                uint32_t db = (uint32_t)__cvta_generic_to_shared(Bb + r * 36 + c);
                CP_ASYNC16(db, W + (size_t)n * K + k0 + c);
            } else {
                *reinterpret_cast<float4*>(Bb + r * 36 + c) = make_float4(0.f, 0.f, 0.f, 0.f);
            }
        }
        CP_COMMIT();
    };

    const int nk = K >> 5;
    stage(0, 0);

    for (int kb = 0; kb < nk; kb++) {
        if (kb + 1 < nk) { stage((kb + 1) << 5, (kb + 1) & 1); CP_WAIT1(); }
        else             { CP_WAIT0(); }
        __syncthreads();

        const float* Ab = sg + (kb & 1) * 9216;
        const float* Bb = Ab + 4608;
#pragma unroll
        for (int ks = 0; ks < 4; ks++) {
            const int kc = ks * 8 + tg;
            uint32_t af[4][4], bf[4][2];
#pragma unroll
            for (int mt = 0; mt < 4; mt++) {
                int rb = wm * 64 + mt * 16 + g;
                af[mt][0] = f2tf(Ab[rb * 36 + kc]);
                af[mt][1] = f2tf(Ab[(rb + 8) * 36 + kc]);
                af[mt][2] = f2tf(Ab[rb * 36 + kc + 4]);
                af[mt][3] = f2tf(Ab[(rb + 8) * 36 + kc + 4]);
            }
#pragma unroll
            for (int nt = 0; nt < 4; nt++) {
                int nb = wn * 32 + nt * 8 + g;
                bf[nt][0] = f2tf(Bb[nb * 36 + kc]);
                bf[nt][1] = f2tf(Bb[nb * 36 + kc + 4]);
            }
#pragma unroll
            for (int mt = 0; mt < 4; mt++)
#pragma unroll
                for (int nt = 0; nt < 4; nt++)
                    MMA_TF32(acc[mt][nt], af[mt][0], af[mt][1], af[mt][2], af[mt][3],
                             bf[nt][0], bf[nt][1]);
        }
        __syncthreads();
    }

#pragma unroll
    for (int mt = 0; mt < 4; mt++) {
        int row = m0 + wm * 64 + mt * 16 + g;
#pragma unroll
        for (int nt = 0; nt < 4; nt++) {
            int col = n0 + wn * 32 + nt * 8 + (tg << 1);
            if (col < N) {
                float2 bv = make_float2(0.f, 0.f);
                if (bias) bv = *reinterpret_cast<const float2*>(bias + col);
                float2 v0 = make_float2(acc[mt][nt][0] + bv.x, acc[mt][nt][1] + bv.y);
                float2 v1 = make_float2(acc[mt][nt][2] + bv.x, acc[mt][nt][3] + bv.y);
                *reinterpret_cast<float2*>(C + (size_t)row * N + col) = v0;
                *reinterpret_cast<float2*>(C + (size_t)(row + 8) * N + col) = v1;
            }
        }
    }
}

// ---------------- RMSNorm (in-place), one block per row --------------------
__global__ void __launch_bounds__(256) rmsnorm_k(float* __restrict__ x,
                                                 const float* __restrict__ w, int D)
{
    const int row = blockIdx.x;
    float* xr = x + (size_t)row * D;
    float ss = 0.f;
    for (int i = threadIdx.x; i < D; i += 256) { float v = xr[i]; ss = fmaf(v, v, ss); }
    __shared__ float red[8];
#pragma unroll
    for (int d = 16; d; d >>= 1) ss += __shfl_xor_sync(0xffffffffu, ss, d);
    if ((threadIdx.x & 31) == 0) red[threadIdx.x >> 5] = ss;
    __syncthreads();
    if (threadIdx.x == 0) {
        float t = 0.f;
#pragma unroll
        for (int i = 0; i < 8; i++) t += red[i];
        red[0] = t;
    }
    __syncthreads();
    const float r = rsqrtf(red[0] / (float)D + 1e-6f);
    for (int i = threadIdx.x; i < D; i += 256) xr[i] = w[i] * (xr[i] * r);
}

// ---------------- RoPE tables (fp64 trig for range safety) ------------------
__global__ void rope_tab_k(float* __restrict__ ct, float* __restrict__ st)
{
    const int pos = blockIdx.x;
    const int j = threadIdx.x;
    double inv = pow(10000.0, -((double)j) / 32.0);
    float ang = (float)pos * (float)inv;
    float c = (float)cos((double)ang);
    float s = (float)sin((double)ang);
    ct[pos * 64 + j] = c; ct[pos * 64 + j + 32] = c;
    st[pos * 64 + j] = s; st[pos * 64 + j + 32] = s;
}

// ---------------- kv split: rmsnorm first 512, rope last 64 -----------------
__global__ void __launch_bounds__(256) kvprep_k(
    const float* __restrict__ kvf, const float* __restrict__ w,
    float* __restrict__ kvn, float* __restrict__ kpe,
    const float* __restrict__ ct, const float* __restrict__ st)
{
    const int row = blockIdx.x;
    const float* xr = kvf + (size_t)row * 576;
    float ss = 0.f;
    for (int i = threadIdx.x; i < 512; i += 256) { float v = xr[i]; ss = fmaf(v, v, ss); }
    __shared__ float red[8];
#pragma unroll
    for (int d = 16; d; d >>= 1) ss += __shfl_xor_sync(0xffffffffu, ss, d);
    if ((threadIdx.x & 31) == 0) red[threadIdx.x >> 5] = ss;
    __syncthreads();
    if (threadIdx.x == 0) {
        float t = 0.f;
#pragma unroll
        for (int i = 0; i < 8; i++) t += red[i];
        red[0] = t;
    }
    __syncthreads();
    const float r = rsqrtf(red[0] / 512.f + 1e-6f);
    for (int i = threadIdx.x; i < 512; i += 256)
        kvn[(size_t)row * 512 + i] = w[i] * (xr[i] * r);

    if (threadIdx.x < 32) {
        const int j = threadIdx.x;
        const int pos = row & (S_ - 1);
        float c = ct[pos * 64 + j], s = st[pos * 64 + j];
        float x1 = xr[512 + j], x2 = xr[544 + j];
        kpe[(size_t)row * 64 + j]      = x1 * c - x2 * s;
        kpe[(size_t)row * 64 + 32 + j] = x2 * c + x1 * s;
    }
}

// ---------------- rope on q_pe slice of each head (in-place) ----------------
__global__ void __launch_bounds__(256) ropeq_k(float* __restrict__ q,
                                               const float* __restrict__ ct,
                                               const float* __restrict__ st)
{
    const int idx = blockIdx.x * 256 + threadIdx.x;
    const int row = idx >> 9;
    const int h = (idx >> 5) & 15;
    const int j = idx & 31;
    const int pos = row & (S_ - 1);
    float* p = q + (size_t)row * 3072 + h * 192 + 128;
    float c = ct[pos * 64 + j], s = st[pos * 64 + j];
    float x1 = p[j], x2 = p[j + 32];
    p[j]      = x1 * c - x2 * s;
    p[j + 32] = x2 * c + x1 * s;
}

// ---------------- flash attention (absorbed MLA), 128-row q-tiles -----------
// qk-dim 192, v-dim 128; tf32 mma m16n8k8, fp32 softmax.
// grid (16, 16, 2); 256 threads = 8 warps: wm=warp>>1 (32 rows), wn=warp&1.
// QK warp tile 32x32 (2 m-tiles x 4 n-tiles); PV warp tile 32x64 (2x8).
// smem 222,208 B -> 1 CTA/SM (reg budget 256: no spill despite 64-reg O acc).
__global__ void __launch_bounds__(256) attn_k(
    const float* __restrict__ Q,    // [4096, 3072]
    const float* __restrict__ KV,   // [32][2048][256]: k_abs | v_abs
    const float* __restrict__ Kpe,  // [4096, 64]
    const int*   __restrict__ msk,  // [2, 2048]
    float* __restrict__ Out)        // [4096, 2048]
{
    const int qb = blockIdx.x, h = blockIdx.y, b = blockIdx.z;
    const int tid = threadIdx.x;
    const int warp = tid >> 5, lane = tid & 31;
    const int wm = warp >> 1, wn = warp & 1;
    const int g = lane >> 2, tg = lane & 3;

    extern __shared__ uint32_t smu[];
    uint32_t* sQ  = smu;                 // [128][196] tf32
    uint32_t* sK  = sQ + 128 * 196;      // [64][196]
    uint32_t* sVT = sK + 64 * 196;       // [128][68] (V transposed)
    uint32_t* sP  = sVT + 128 * 68;      // [128][68]
    float* sM = (float*)(sP + 128 * 68); // [2][128]
    float* sS = sM + 256;                // [2][128]

    const int s0 = qb * 128;
    const float* Qb = Q + (size_t)(b * 2048 + s0) * 3072 + h * 192;
    for (int idx = tid; idx < 128 * 48; idx += 256) {
        int r = idx / 48, c4 = idx % 48;
        float4 v = *reinterpret_cast<const float4*>(Qb + (size_t)r * 3072 + c4 * 4);
        uint32_t* d = sQ + r * 196 + c4 * 4;
        d[0] = f2tf(v.x); d[1] = f2tf(v.y); d[2] = f2tf(v.z); d[3] = f2tf(v.w);
    }

    const float scale = 0.07216878364870322f;  // 1/sqrt(192)
    // 4 owned rows: q = mt*2 + p  ->  local row wm*32 + mt*16 + p*8 + g
    int rloc[4], sg_[4];
#pragma unroll
    for (int q = 0; q < 4; q++) {
        rloc[q] = wm * 32 + (q >> 1) * 16 + (q & 1) * 8 + g;
        sg_[q] = s0 + rloc[q];
    }

    float m_i[4], l_i[4], o[2][8][4];
#pragma unroll
    for (int q = 0; q < 4; q++) { m_i[q] = -3.0e38f; l_i[q] = 0.f; }
#pragma unroll
    for (int mt = 0; mt < 2; mt++)
#pragma unroll
        for (int nt = 0; nt < 8; nt++)
#pragma unroll
            for (int r = 0; r < 4; r++) o[mt][nt][r] = 0.f;

    const int* mrow = msk + (size_t)b * 2048;
    const int nkt = 2 * qb + 2;

    for (int kt = 0; kt < nkt; kt++) {
        __syncthreads();
        const float* KVb = KV + ((size_t)(b * 16 + h) * 2048 + kt * 64) * 256;
        for (int idx = tid; idx < 64 * 64; idx += 256) {
            int r = idx >> 6, c4 = idx & 63;
            float4 v = *reinterpret_cast<const float4*>(KVb + (size_t)r * 256 + c4 * 4);
            if (c4 < 32) {
                uint32_t* d = sK + r * 196 + c4 * 4;
                d[0] = f2tf(v.x); d[1] = f2tf(v.y); d[2] = f2tf(v.z); d[3] = f2tf(v.w);
            } else {
                int vc = (c4 - 32) * 4;
                sVT[(vc + 0) * 68 + r] = f2tf(v.x);
                sVT[(vc + 1) * 68 + r] = f2tf(v.y);
                sVT[(vc + 2) * 68 + r] = f2tf(v.z);
                sVT[(vc + 3) * 68 + r] = f2tf(v.w);
            }
        }
        const float* Kpb = Kpe + (size_t)(b * 2048 + kt * 64) * 64;
        for (int idx = tid; idx < 64 * 16; idx += 256) {
            int r = idx >> 4, c4 = idx & 15;
            float4 v = *reinterpret_cast<const float4*>(Kpb + (size_t)r * 64 + c4 * 4);
            uint32_t* d = sK + r * 196 + 128 + c4 * 4;
            d[0] = f2tf(v.x); d[1] = f2tf(v.y); d[2] = f2tf(v.z); d[3] = f2tf(v.w);
        }
        __syncthreads();

        // ---- scores: 32x32 per warp over 192-dim contraction ----
        float sc[2][4][4];
#pragma unroll
        for (int mt = 0; mt < 2; mt++)
#pragma unroll
            for (int nt = 0; nt < 4; nt++)
#pragma unroll
                for (int r = 0; r < 4; r++) sc[mt][nt][r] = 0.f;

#pragma unroll
        for (int ks = 0; ks < 24; ks++) {
            const int kc = ks * 8 + tg;
            uint32_t a[2][4];
#pragma unroll
            for (int mt = 0; mt < 2; mt++) {
                const uint32_t* aq = sQ + (wm * 32 + mt * 16 + g) * 196 + kc;
                a[mt][0] = aq[0]; a[mt][1] = aq[8 * 196];
                a[mt][2] = aq[4]; a[mt][3] = aq[8 * 196 + 4];
            }
#pragma unroll
            for (int nt = 0; nt < 4; nt++) {
                const uint32_t* bk = sK + (wn * 32 + nt * 8 + g) * 196 + kc;
                uint32_t b0 = bk[0], b1 = bk[4];
#pragma unroll
                for (int mt = 0; mt < 2; mt++)
                    MMA_TF32(sc[mt][nt], a[mt][0], a[mt][1], a[mt][2], a[mt][3], b0, b1);
            }
        }

        // ---- scale + mask + row max ----
        const bool diag = (kt >= 2 * qb);
        float tmax[4] = {-3.0e38f, -3.0e38f, -3.0e38f, -3.0e38f};
#pragma unroll
        for (int mt = 0; mt < 2; mt++)
#pragma unroll
            for (int nt = 0; nt < 4; nt++) {
                int t0 = kt * 64 + wn * 32 + nt * 8 + 2 * tg, t1 = t0 + 1;
                int mv0 = mrow[t0], mv1 = mrow[t1];
                float v0 = sc[mt][nt][0] * scale; if ((diag && t0 > sg_[mt * 2]) || mv0 == 0) v0 = -1e15f;
                float v1 = sc[mt][nt][1] * scale; if ((diag && t1 > sg_[mt * 2]) || mv1 == 0) v1 = -1e15f;
                float v2 = sc[mt][nt][2] * scale; if ((diag && t0 > sg_[mt * 2 + 1]) || mv0 == 0) v2 = -1e15f;
                float v3 = sc[mt][nt][3] * scale; if ((diag && t1 > sg_[mt * 2 + 1]) || mv1 == 0) v3 = -1e15f;
                sc[mt][nt][0] = v0; sc[mt][nt][1] = v1; sc[mt][nt][2] = v2; sc[mt][nt][3] = v3;
                tmax[mt * 2]     = fmaxf(tmax[mt * 2],     fmaxf(v0, v1));
                tmax[mt * 2 + 1] = fmaxf(tmax[mt * 2 + 1], fmaxf(v2, v3));
            }
#pragma unroll
        for (int q = 0; q < 4; q++) {
            tmax[q] = fmaxf(tmax[q], __shfl_xor_sync(0xffffffffu, tmax[q], 1));
            tmax[q] = fmaxf(tmax[q], __shfl_xor_sync(0xffffffffu, tmax[q], 2));
        }
        if (tg == 0)
#pragma unroll
            for (int q = 0; q < 4; q++) sM[wn * 128 + rloc[q]] = tmax[q];
        __syncthreads();

        float al[4];
#pragma unroll
        for (int q = 0; q < 4; q++) {
            float nm = fmaxf(m_i[q], fmaxf(sM[rloc[q]], sM[128 + rloc[q]]));
            al[q] = expf(m_i[q] - nm);
            m_i[q] = nm;
        }

        // ---- exp + P store (tf32) + row sum ----
        float ls[4] = {0.f, 0.f, 0.f, 0.f};
#pragma unroll
        for (int mt = 0; mt < 2; mt++)
#pragma unroll
            for (int nt = 0; nt < 4; nt++) {
                float p0 = expf(sc[mt][nt][0] - m_i[mt * 2]);
                float p1 = expf(sc[mt][nt][1] - m_i[mt * 2]);
                float p2 = expf(sc[mt][nt][2] - m_i[mt * 2 + 1]);
                float p3 = expf(sc[mt][nt][3] - m_i[mt * 2 + 1]);
                ls[mt * 2] += p0 + p1; ls[mt * 2 + 1] += p2 + p3;
                int jc = wn * 32 + nt * 8 + 2 * tg;
                sP[rloc[mt * 2]     * 68 + jc]     = f2tf(p0);
                sP[rloc[mt * 2]     * 68 + jc + 1] = f2tf(p1);
                sP[rloc[mt * 2 + 1] * 68 + jc]     = f2tf(p2);
                sP[rloc[mt * 2 + 1] * 68 + jc + 1] = f2tf(p3);
            }
#pragma unroll
        for (int q = 0; q < 4; q++) {
            ls[q] += __shfl_xor_sync(0xffffffffu, ls[q], 1);
            ls[q] += __shfl_xor_sync(0xffffffffu, ls[q], 2);
        }
        if (tg == 0)
#pragma unroll
            for (int q = 0; q < 4; q++) sS[wn * 128 + rloc[q]] = ls[q];
        __syncthreads();

#pragma unroll
        for (int q = 0; q < 4; q++)
            l_i[q] = l_i[q] * al[q] + sS[rloc[q]] + sS[128 + rloc[q]];

        // ---- O rescale + PV: 32x64 per warp over 64-dim contraction ----
#pragma unroll
        for (int mt = 0; mt < 2; mt++)
#pragma unroll
            for (int nt = 0; nt < 8; nt++) {
                o[mt][nt][0] *= al[mt * 2];     o[mt][nt][1] *= al[mt * 2];
                o[mt][nt][2] *= al[mt * 2 + 1]; o[mt][nt][3] *= al[mt * 2 + 1];
            }
#pragma unroll
        for (int ks = 0; ks < 8; ks++) {
            const int kc = ks * 8 + tg;
            uint32_t a[2][4];
#pragma unroll
            for (int mt = 0; mt < 2; mt++) {
                const uint32_t* ap = sP + (wm * 32 + mt * 16 + g) * 68 + kc;
                a[mt][0] = ap[0]; a[mt][1] = ap[8 * 68];
                a[mt][2] = ap[4]; a[mt][3] = ap[8 * 68 + 4];
            }
#pragma unroll
            for (int nt = 0; nt < 8; nt++) {
                const uint32_t* bv = sVT + (wn * 64 + nt * 8 + g) * 68 + kc;
                uint32_t b0 = bv[0], b1 = bv[4];
#pragma unroll
                for (int mt = 0; mt < 2; mt++)
                    MMA_TF32(o[mt][nt], a[mt][0], a[mt][1], a[mt][2], a[mt][3], b0, b1);
            }
        }
    }

    // ---- epilogue ----
#pragma unroll
    for (int mt = 0; mt < 2; mt++) {
        float i1 = 1.f / l_i[mt * 2], i2 = 1.f / l_i[mt * 2 + 1];
        float* orow1 = Out + (size_t)(b * 2048 + sg_[mt * 2])     * 2048 + h * 128;
        float* orow2 = Out + (size_t)(b * 2048 + sg_[mt * 2 + 1]) * 2048 + h * 128;
#pragma unroll
        for (int nt = 0; nt < 8; nt++) {
            int c = wn * 64 + nt * 8 + 2 * tg;
            *reinterpret_cast<float2*>(orow1 + c) =
                make_float2(o[mt][nt][0] * i1, o[mt][nt][1] * i1);
            *reinterpret_cast<float2*>(orow2 + c) =
                make_float2(o[mt][nt][2] * i2, o[mt][nt][3] * i2);
        }
    }
}

// ------------------------------- host side ---------------------------------
extern "C" void kernel_launch(void* const* d_in, const int* in_sizes, int n_in,
                              void* d_out, int out_size)
{
    (void)in_sizes; (void)n_in; (void)out_size;
    const float* x        = (const float*)d_in[0];
    const int*   mask     = (const int*)  d_in[1];
    const float* wq_a_w   = (const float*)d_in[2];
    const float* wq_a_b   = (const float*)d_in[3];
    const float* q_norm_w = (const float*)d_in[4];
    const float* wq_b_w   = (const float*)d_in[5];
    const float* wq_b_b   = (const float*)d_in[6];
    const float* wkv_a_w  = (const float*)d_in[7];
    const float* wkv_a_b  = (const float*)d_in[8];
    const float* kv_norm_w= (const float*)d_in[9];
    const float* wkv_b_w  = (const float*)d_in[10];
    const float* wo_w     = (const float*)d_in[11];
    const float* wo_b     = (const float*)d_in[12];
    float* out = (float*)d_out;

    float *qa, *q, *kvf, *kvn, *kpe, *kvab, *att, *ct, *st;
    cudaGetSymbolAddress((void**)&qa,   g_qa);
    cudaGetSymbolAddress((void**)&q,    g_q);
    cudaGetSymbolAddress((void**)&kvf,  g_kvf);
    cudaGetSymbolAddress((void**)&kvn,  g_kvn);
    cudaGetSymbolAddress((void**)&kpe,  g_kpe);
    cudaGetSymbolAddress((void**)&kvab, g_kvab);
    cudaGetSymbolAddress((void**)&att,  g_att);
    cudaGetSymbolAddress((void**)&ct,   g_cos);
    cudaGetSymbolAddress((void**)&st,   g_sin);

    const int gemm_smem = 2 * 9216 * 4;   // 73,728 B (2 fp32 stages)
    cudaFuncSetAttribute(sgemm_bias, cudaFuncAttributeMaxDynamicSharedMemorySize, gemm_smem);

    rope_tab_k<<<S_, 32>>>(ct, st);

    // q_a = x @ wq_a^T + b   [4096,2048]x[1536,2048]
    { dim3 g(QL_ / 128, ROWS_ / 128, 1);
      sgemm_bias<<<g, 256, gemm_smem>>>(x, wq_a_w, wq_a_b, qa, ROWS_, QL_, H_, 1, 0, 1, 0, 0); }
    rmsnorm_k<<<ROWS_, 256>>>(qa, q_norm_w, QL_);
    // q = q_a @ wq_b^T + b   [4096,1536]x[3072,1536]
    { dim3 g((NH_ * QKH_) / 128, ROWS_ / 128, 1);
      sgemm_bias<<<g, 256, gemm_smem>>>(qa, wq_b_w, wq_b_b, q, ROWS_, NH_ * QKH_, QL_, 1, 0, 1, 0, 0); }
    // kv_full = x @ wkv_a^T + b   [4096,2048]x[576,2048]
    { dim3 g((KVL_ + ROPE_ + 127) / 128, ROWS_ / 128, 1);
      sgemm_bias<<<g, 256, gemm_smem>>>(x, wkv_a_w, wkv_a_b, kvf, ROWS_, KVL_ + ROPE_, H_, 1, 0, 1, 0, 0); }
    kvprep_k<<<ROWS_, 256>>>(kvf, kv_norm_w, kvn, kpe, ct, st);
    ropeq_k<<<(ROWS_ * NH_ * 32) / 256, 256>>>(q, ct, st);

    // absorbed K/V: per (b,h): kvab[z] = kvn[b] (2048x512) @ wkv_b[h] (256x512)^T
    { dim3 g(256 / 128, S_ / 128, B_ * NH_);
      sgemm_bias<<<g, 256, gemm_smem>>>(kvn, wkv_b_w, nullptr, kvab, S_, 256, KVL_,
                             NH_, (long long)S_ * KVL_,
                             NH_, 256LL * KVL_,
                             (long long)S_ * 256); }

    // flash attention (tensor-core, 128-row q-tiles)
    // smem words: sQ 128*196 + sK 64*196 + sVT 128*68 + sP 128*68 = 55040
    // plus sM (2*128) + sS (2*128) floats = 512 words -> (55040+512)*4 = 222,208 B
    const int attn_smem = (128 * 196 + 64 * 196 + 128 * 68 + 128 * 68 + 512) * 4;
    cudaFuncSetAttribute(attn_k, cudaFuncAttributeMaxDynamicSharedMemorySize, attn_smem);
    attn_k<<<dim3(S_ / 128, NH_, B_), 256, attn_smem>>>(q, kvab, kpe, mask, att);

    // out = att @ wo^T + b   [4096,2048]x[2048,2048]
    { dim3 g(H_ / 128, ROWS_ / 128, 1);
      sgemm_bias<<<g, 256, gemm_smem>>>(att, wo_w, wo_b, out, ROWS_, H_, NH_ * VD_, 1, 0, 1, 0, 0); }
}

// round 15
// speedup vs baseline: 1.4147x; 1.0090x over previous
#include <cuda_runtime.h>
#include <math.h>
#include <stddef.h>
#include <stdint.h>

// MLA shapes (compile-time constants)
#define B_    2
#define S_    2048
#define H_    2048
#define NH_   16
#define QL_   1536
#define KVL_  512
#define NOPE_ 128
#define ROPE_ 64
#define VD_   128
#define QKH_  192
#define ROWS_ (B_*S_)   // 4096

// ---------------- scratch (device globals: no allocs allowed) ----------------
__device__ float g_qa  [(size_t)ROWS_*QL_];
__device__ float g_q   [(size_t)ROWS_*NH_*QKH_];
__device__ float g_kvf [(size_t)ROWS_*(KVL_+ROPE_)];
__device__ float g_kvn [(size_t)ROWS_*KVL_];
__device__ float g_kpe [(size_t)ROWS_*ROPE_];
__device__ float g_kvab[(size_t)B_*NH_*S_*256];
__device__ float g_att [(size_t)ROWS_*NH_*VD_];
__device__ float g_cos [(size_t)S_*ROPE_];
__device__ float g_sin [(size_t)S_*ROPE_];

// ---------------- tf32 helpers ----------------
__device__ __forceinline__ uint32_t f2tf(float x) {
    uint32_t r;
    asm("cvt.rna.tf32.f32 %0, %1;" : "=r"(r) : "f"(x));
    return r;
}

#define MMA_TF32(d, a0, a1, a2, a3, b0, b1)                                  \
    asm volatile(                                                            \
        "mma.sync.aligned.m16n8k8.row.col.f32.tf32.tf32.f32 "                \
        "{%0,%1,%2,%3}, {%4,%5,%6,%7}, {%8,%9}, {%0,%1,%2,%3};"              \
        : "+f"((d)[0]), "+f"((d)[1]), "+f"((d)[2]), "+f"((d)[3])             \
        : "r"(a0), "r"(a1), "r"(a2), "r"(a3), "r"(b0), "r"(b1))

#define CP_ASYNC16(dst, src) \
    asm volatile("cp.async.ca.shared.global [%0], [%1], 16;" :: "r"(dst), "l"(src))
#define CP_COMMIT()  asm volatile("cp.async.commit_group;")
#define CP_WAIT1()   asm volatile("cp.async.wait_group 1;")
#define CP_WAIT0()   asm volatile("cp.async.wait_group 0;")

// ---------------- tensor-core GEMM: C = A(MxK) @ W(NxK)^T + bias ------------
// (round-12 proven) tf32 mma m16n8k8, 128x128 tile, BK=32, cp.async 2-stage.
__global__ void __launch_bounds__(256, 2) sgemm_bias(
    const float* __restrict__ A, const float* __restrict__ W,
    const float* __restrict__ bias, float* __restrict__ C,
    int M, int N, int K,
    int zdA, long long sA, int zmB, long long sB, long long sC)
{
    extern __shared__ float sg[];   // 2 stages x (A 128*36 + B 128*36) fp32

    const int z = blockIdx.z;
    A += (long long)(z / zdA) * sA;
    W += (long long)(z % zmB) * sB;
    C += (long long)z * sC;

    const int tid  = threadIdx.x;
    const int warp = tid >> 5, lane = tid & 31;
    const int wm = warp >> 2;
    const int wn = warp & 3;
    const int g  = lane >> 2;
    const int tg = lane & 3;
    const int m0 = blockIdx.y * 128;
    const int n0 = blockIdx.x * 128;

    float acc[4][4][4];
#pragma unroll
    for (int mt = 0; mt < 4; mt++)
#pragma unroll
        for (int nt = 0; nt < 4; nt++)
#pragma unroll
            for (int r = 0; r < 4; r++) acc[mt][nt][r] = 0.f;

    auto stage = [&](int k0, int s) {
        float* Ab = sg + s * 9216;
        float* Bb = Ab + 4608;
#pragma unroll
        for (int it = 0; it < 4; it++) {
            int idx = tid + it * 256;
            int r = idx >> 3;
            int c = (idx & 7) << 2;
            uint32_t da = (uint32_t)__cvta_generic_to_shared(Ab + r * 36 + c);
            CP_ASYNC16(da, A + (size_t)(m0 + r) * K + k0 + c);
            int n = n0 + r;
            if (n < N) {
                uint32_t db = (uint32_t)__cvta_generic_to_shared(Bb + r * 36 + c);
                CP_ASYNC16(db, W + (size_t)n * K + k0 + c);
            } else {
                *reinterpret_cast<float4*>(Bb + r * 36 + c) = make_float4(0.f, 0.f, 0.f, 0.f);
            }
        }
        CP_COMMIT();
    };

    const int nk = K >> 5;
    stage(0, 0);

    for (int kb = 0; kb < nk; kb++) {
        if (kb + 1 < nk) { stage((kb + 1) << 5, (kb + 1) & 1); CP_WAIT1(); }
        else             { CP_WAIT0(); }
        __syncthreads();

        const float* Ab = sg + (kb & 1) * 9216;
        const float* Bb = Ab + 4608;
#pragma unroll
        for (int ks = 0; ks < 4; ks++) {
            const int kc = ks * 8 + tg;
            uint32_t af[4][4], bf[4][2];
#pragma unroll
            for (int mt = 0; mt < 4; mt++) {
                int rb = wm * 64 + mt * 16 + g;
                af[mt][0] = f2tf(Ab[rb * 36 + kc]);
                af[mt][1] = f2tf(Ab[(rb + 8) * 36 + kc]);
                af[mt][2] = f2tf(Ab[rb * 36 + kc + 4]);
                af[mt][3] = f2tf(Ab[(rb + 8) * 36 + kc + 4]);
            }
#pragma unroll
            for (int nt = 0; nt < 4; nt++) {
                int nb = wn * 32 + nt * 8 + g;
                bf[nt][0] = f2tf(Bb[nb * 36 + kc]);
                bf[nt][1] = f2tf(Bb[nb * 36 + kc + 4]);
            }
#pragma unroll
            for (int mt = 0; mt < 4; mt++)
#pragma unroll
                for (int nt = 0; nt < 4; nt++)
                    MMA_TF32(acc[mt][nt], af[mt][0], af[mt][1], af[mt][2], af[mt][3],
                             bf[nt][0], bf[nt][1]);
        }
        __syncthreads();
    }

#pragma unroll
    for (int mt = 0; mt < 4; mt++) {
        int row = m0 + wm * 64 + mt * 16 + g;
#pragma unroll
        for (int nt = 0; nt < 4; nt++) {
            int col = n0 + wn * 32 + nt * 8 + (tg << 1);
            if (col < N) {
                float2 bv = make_float2(0.f, 0.f);
                if (bias) bv = *reinterpret_cast<const float2*>(bias + col);
                float2 v0 = make_float2(acc[mt][nt][0] + bv.x, acc[mt][nt][1] + bv.y);
                float2 v1 = make_float2(acc[mt][nt][2] + bv.x, acc[mt][nt][3] + bv.y);
                *reinterpret_cast<float2*>(C + (size_t)row * N + col) = v0;
                *reinterpret_cast<float2*>(C + (size_t)(row + 8) * N + col) = v1;
            }
        }
    }
}

// ---------------- RMSNorm (in-place), one block per row --------------------
__global__ void __launch_bounds__(256) rmsnorm_k(float* __restrict__ x,
                                                 const float* __restrict__ w, int D)
{
    const int row = blockIdx.x;
    float* xr = x + (size_t)row * D;
    float ss = 0.f;
    for (int i = threadIdx.x; i < D; i += 256) { float v = xr[i]; ss = fmaf(v, v, ss); }
    __shared__ float red[8];
#pragma unroll
    for (int d = 16; d; d >>= 1) ss += __shfl_xor_sync(0xffffffffu, ss, d);
    if ((threadIdx.x & 31) == 0) red[threadIdx.x >> 5] = ss;
    __syncthreads();
    if (threadIdx.x == 0) {
        float t = 0.f;
#pragma unroll
        for (int i = 0; i < 8; i++) t += red[i];
        red[0] = t;
    }
    __syncthreads();
    const float r = rsqrtf(red[0] / (float)D + 1e-6f);
    for (int i = threadIdx.x; i < D; i += 256) xr[i] = w[i] * (xr[i] * r);
}

// ---------------- RoPE tables (fp64 trig for range safety) ------------------
__global__ void rope_tab_k(float* __restrict__ ct, float* __restrict__ st)
{
    const int pos = blockIdx.x;
    const int j = threadIdx.x;
    double inv = pow(10000.0, -((double)j) / 32.0);
    float ang = (float)pos * (float)inv;
    float c = (float)cos((double)ang);
    float s = (float)sin((double)ang);
    ct[pos * 64 + j] = c; ct[pos * 64 + j + 32] = c;
    st[pos * 64 + j] = s; st[pos * 64 + j + 32] = s;
}

// ---------------- kv split: rmsnorm first 512, rope last 64 -----------------
__global__ void __launch_bounds__(256) kvprep_k(
    const float* __restrict__ kvf, const float* __restrict__ w,
    float* __restrict__ kvn, float* __restrict__ kpe,
    const float* __restrict__ ct, const float* __restrict__ st)
{
    const int row = blockIdx.x;
    const float* xr = kvf + (size_t)row * 576;
    float ss = 0.f;
    for (int i = threadIdx.x; i < 512; i += 256) { float v = xr[i]; ss = fmaf(v, v, ss); }
    __shared__ float red[8];
#pragma unroll
    for (int d = 16; d; d >>= 1) ss += __shfl_xor_sync(0xffffffffu, ss, d);
    if ((threadIdx.x & 31) == 0) red[threadIdx.x >> 5] = ss;
    __syncthreads();
    if (threadIdx.x == 0) {
        float t = 0.f;
#pragma unroll
        for (int i = 0; i < 8; i++) t += red[i];
        red[0] = t;
    }
    __syncthreads();
    const float r = rsqrtf(red[0] / 512.f + 1e-6f);
    for (int i = threadIdx.x; i < 512; i += 256)
        kvn[(size_t)row * 512 + i] = w[i] * (xr[i] * r);

    if (threadIdx.x < 32) {
        const int j = threadIdx.x;
        const int pos = row & (S_ - 1);
        float c = ct[pos * 64 + j], s = st[pos * 64 + j];
        float x1 = xr[512 + j], x2 = xr[544 + j];
        kpe[(size_t)row * 64 + j]      = x1 * c - x2 * s;
        kpe[(size_t)row * 64 + 32 + j] = x2 * c + x1 * s;
    }
}

// ---------------- rope on q_pe slice of each head (in-place) ----------------
__global__ void __launch_bounds__(256) ropeq_k(float* __restrict__ q,
                                               const float* __restrict__ ct,
                                               const float* __restrict__ st)
{
    const int idx = blockIdx.x * 256 + threadIdx.x;
    const int row = idx >> 9;
    const int h = (idx >> 5) & 15;
    const int j = idx & 31;
    const int pos = row & (S_ - 1);
    float* p = q + (size_t)row * 3072 + h * 192 + 128;
    float c = ct[pos * 64 + j], s = st[pos * 64 + j];
    float x1 = p[j], x2 = p[j + 32];
    p[j]      = x1 * c - x2 * s;
    p[j + 32] = x2 * c + x1 * s;
}

// ---------------- flash attention (absorbed MLA), 128-row q-tiles -----------
// Warp-row-ownership: 8 warps x 16 full rows. QK warp tile 16x64 (8 n-tiles),
// PV 16x128 (16 n-tiles). Softmax purely quad-shuffle local (no smem
// exchange); sP is warp-private -> __syncwarp only. 2 block syncs/tile.
__global__ void __launch_bounds__(256) attn_k(
    const float* __restrict__ Q,    // [4096, 3072]
    const float* __restrict__ KV,   // [32][2048][256]: k_abs | v_abs
    const float* __restrict__ Kpe,  // [4096, 64]
    const int*   __restrict__ msk,  // [2, 2048]
    float* __restrict__ Out)        // [4096, 2048]
{
    const int qb = blockIdx.x, h = blockIdx.y, b = blockIdx.z;
    const int tid = threadIdx.x;
    const int warp = tid >> 5, lane = tid & 31;
    const int g = lane >> 2, tg = lane & 3;
    const int w16 = warp * 16;

    extern __shared__ uint32_t smu[];
    uint32_t* sQ  = smu;                 // [128][196] tf32
    uint32_t* sK  = sQ + 128 * 196;      // [64][196]
    uint32_t* sVT = sK + 64 * 196;       // [128][68] (V transposed)
    uint32_t* sP  = sVT + 128 * 68;      // [128][68] (warp-private 16-row slices)

    const int s0 = qb * 128;
    const float* Qb = Q + (size_t)(b * 2048 + s0) * 3072 + h * 192;
    for (int idx = tid; idx < 128 * 48; idx += 256) {
        int r = idx / 48, c4 = idx % 48;
        float4 v = *reinterpret_cast<const float4*>(Qb + (size_t)r * 3072 + c4 * 4);
        uint32_t* d = sQ + r * 196 + c4 * 4;
        d[0] = f2tf(v.x); d[1] = f2tf(v.y); d[2] = f2tf(v.z); d[3] = f2tf(v.w);
    }

    const float scale = 0.07216878364870322f;  // 1/sqrt(192)
    const int r1 = w16 + g, r2 = r1 + 8;       // the two rows this thread owns
    const int sg1 = s0 + r1, sg2 = s0 + r2;

    float m1 = -3.0e38f, m2 = -3.0e38f, l1 = 0.f, l2 = 0.f;
    float o[16][4];
#pragma unroll
    for (int nt = 0; nt < 16; nt++)
#pragma unroll
        for (int r = 0; r < 4; r++) o[nt][r] = 0.f;

    const int* mrow = msk + (size_t)b * 2048;
    const int nkt = 2 * qb + 2;

    for (int kt = 0; kt < nkt; kt++) {
        __syncthreads();   // also covers Q staging on the first iteration
        const float* KVb = KV + ((size_t)(b * 16 + h) * 2048 + kt * 64) * 256;
        for (int idx = tid; idx < 64 * 64; idx += 256) {
            int r = idx >> 6, c4 = idx & 63;
            float4 v = *reinterpret_cast<const float4*>(KVb + (size_t)r * 256 + c4 * 4);
            if (c4 < 32) {
                uint32_t* d = sK + r * 196 + c4 * 4;
                d[0] = f2tf(v.x); d[1] = f2tf(v.y); d[2] = f2tf(v.z); d[3] = f2tf(v.w);
            } else {
                int vc = (c4 - 32) * 4;
                sVT[(vc + 0) * 68 + r] = f2tf(v.x);
                sVT[(vc + 1) * 68 + r] = f2tf(v.y);
                sVT[(vc + 2) * 68 + r] = f2tf(v.z);
                sVT[(vc + 3) * 68 + r] = f2tf(v.w);
            }
        }
        const float* Kpb = Kpe + (size_t)(b * 2048 + kt * 64) * 64;
        for (int idx = tid; idx < 64 * 16; idx += 256) {
            int r = idx >> 4, c4 = idx & 15;
            float4 v = *reinterpret_cast<const float4*>(Kpb + (size_t)r * 64 + c4 * 4);
            uint32_t* d = sK + r * 196 + 128 + c4 * 4;
            d[0] = f2tf(v.x); d[1] = f2tf(v.y); d[2] = f2tf(v.z); d[3] = f2tf(v.w);
        }
        __syncthreads();

        // ---- scores: 16x64 per warp over 192-dim contraction ----
        float sc[8][4];
#pragma unroll
        for (int nt = 0; nt < 8; nt++)
#pragma unroll
            for (int r = 0; r < 4; r++) sc[nt][r] = 0.f;

#pragma unroll
        for (int ks = 0; ks < 24; ks++) {
            const int kc = ks * 8 + tg;
            const uint32_t* aq = sQ + r1 * 196 + kc;
            uint32_t a0 = aq[0], a1 = aq[8 * 196], a2 = aq[4], a3 = aq[8 * 196 + 4];
#pragma unroll
            for (int nt = 0; nt < 8; nt++) {
                const uint32_t* bk = sK + (nt * 8 + g) * 196 + kc;
                MMA_TF32(sc[nt], a0, a1, a2, a3, bk[0], bk[4]);
            }
        }

        // ---- scale + mask + row max (warp-local, full 64 cols) ----
        const bool diag = (kt >= 2 * qb);
        float tm1 = -3.0e38f, tm2 = -3.0e38f;
#pragma unroll
        for (int nt = 0; nt < 8; nt++) {
            int t0 = kt * 64 + nt * 8 + 2 * tg, t1 = t0 + 1;
            int mv0 = mrow[t0], mv1 = mrow[t1];
            float v0 = sc[nt][0] * scale; if ((diag && t0 > sg1) || mv0 == 0) v0 = -1e15f;
            float v1 = sc[nt][1] * scale; if ((diag && t1 > sg1) || mv1 == 0) v1 = -1e15f;
            float v2 = sc[nt][2] * scale; if ((diag && t0 > sg2) || mv0 == 0) v2 = -1e15f;
            float v3 = sc[nt][3] * scale; if ((diag && t1 > sg2) || mv1 == 0) v3 = -1e15f;
            sc[nt][0] = v0; sc[nt][1] = v1; sc[nt][2] = v2; sc[nt][3] = v3;
            tm1 = fmaxf(tm1, fmaxf(v0, v1));
            tm2 = fmaxf(tm2, fmaxf(v2, v3));
        }
        tm1 = fmaxf(tm1, __shfl_xor_sync(0xffffffffu, tm1, 1));
        tm1 = fmaxf(tm1, __shfl_xor_sync(0xffffffffu, tm1, 2));
        tm2 = fmaxf(tm2, __shfl_xor_sync(0xffffffffu, tm2, 1));
        tm2 = fmaxf(tm2, __shfl_xor_sync(0xffffffffu, tm2, 2));

        float nm1 = fmaxf(m1, tm1), nm2 = fmaxf(m2, tm2);
        float al1 = expf(m1 - nm1), al2 = expf(m2 - nm2);
        m1 = nm1; m2 = nm2;

        // ---- exp + P store (tf32, warp-private rows) + row sum ----
        float ls1 = 0.f, ls2 = 0.f;
#pragma unroll
        for (int nt = 0; nt < 8; nt++) {
            float p0 = expf(sc[nt][0] - nm1);
            float p1 = expf(sc[nt][1] - nm1);
            float p2 = expf(sc[nt][2] - nm2);
            float p3 = expf(sc[nt][3] - nm2);
            ls1 += p0 + p1; ls2 += p2 + p3;
            int jc = nt * 8 + 2 * tg;
            sP[r1 * 68 + jc]     = f2tf(p0);
            sP[r1 * 68 + jc + 1] = f2tf(p1);
            sP[r2 * 68 + jc]     = f2tf(p2);
            sP[r2 * 68 + jc + 1] = f2tf(p3);
        }
        ls1 += __shfl_xor_sync(0xffffffffu, ls1, 1);
        ls1 += __shfl_xor_sync(0xffffffffu, ls1, 2);
        ls2 += __shfl_xor_sync(0xffffffffu, ls2, 1);
        ls2 += __shfl_xor_sync(0xffffffffu, ls2, 2);
        l1 = l1 * al1 + ls1;
        l2 = l2 * al2 + ls2;
        __syncwarp();

        // ---- O rescale + PV: 16x128 per warp over 64-dim contraction ----
#pragma unroll
        for (int nt = 0; nt < 16; nt++) {
            o[nt][0] *= al1; o[nt][1] *= al1; o[nt][2] *= al2; o[nt][3] *= al2;
        }
#pragma unroll
        for (int ks = 0; ks < 8; ks++) {
            const int kc = ks * 8 + tg;
            const uint32_t* ap = sP + r1 * 68 + kc;
            uint32_t a0 = ap[0], a1 = ap[8 * 68], a2 = ap[4], a3 = ap[8 * 68 + 4];
#pragma unroll
            for (int nt = 0; nt < 16; nt++) {
                const uint32_t* bv = sVT + (nt * 8 + g) * 68 + kc;
                MMA_TF32(o[nt], a0, a1, a2, a3, bv[0], bv[4]);
            }
        }
    }

    // ---- epilogue ----
    const float i1 = 1.f / l1, i2 = 1.f / l2;
    float* orow1 = Out + (size_t)(b * 2048 + sg1) * 2048 + h * 128;
    float* orow2 = Out + (size_t)(b * 2048 + sg2) * 2048 + h * 128;
#pragma unroll
    for (int nt = 0; nt < 16; nt++) {
        int c = nt * 8 + 2 * tg;
        *reinterpret_cast<float2*>(orow1 + c) = make_float2(o[nt][0] * i1, o[nt][1] * i1);
        *reinterpret_cast<float2*>(orow2 + c) = make_float2(o[nt][2] * i2, o[nt][3] * i2);
    }
}

// ------------------------------- host side ---------------------------------
extern "C" void kernel_launch(void* const* d_in, const int* in_sizes, int n_in,
                              void* d_out, int out_size)
{
    (void)in_sizes; (void)n_in; (void)out_size;
    const float* x        = (const float*)d_in[0];
    const int*   mask     = (const int*)  d_in[1];
    const float* wq_a_w   = (const float*)d_in[2];
    const float* wq_a_b   = (const float*)d_in[3];
    const float* q_norm_w = (const float*)d_in[4];
    const float* wq_b_w   = (const float*)d_in[5];
    const float* wq_b_b   = (const float*)d_in[6];
    const float* wkv_a_w  = (const float*)d_in[7];
    const float* wkv_a_b  = (const float*)d_in[8];
    const float* kv_norm_w= (const float*)d_in[9];
    const float* wkv_b_w  = (const float*)d_in[10];
    const float* wo_w     = (const float*)d_in[11];
    const float* wo_b     = (const float*)d_in[12];
    float* out = (float*)d_out;

    float *qa, *q, *kvf, *kvn, *kpe, *kvab, *att, *ct, *st;
    cudaGetSymbolAddress((void**)&qa,   g_qa);
    cudaGetSymbolAddress((void**)&q,    g_q);
    cudaGetSymbolAddress((void**)&kvf,  g_kvf);
    cudaGetSymbolAddress((void**)&kvn,  g_kvn);
    cudaGetSymbolAddress((void**)&kpe,  g_kpe);
    cudaGetSymbolAddress((void**)&kvab, g_kvab);
    cudaGetSymbolAddress((void**)&att,  g_att);
    cudaGetSymbolAddress((void**)&ct,   g_cos);
    cudaGetSymbolAddress((void**)&st,   g_sin);

    const int gemm_smem = 2 * 9216 * 4;   // 73,728 B (2 fp32 stages)
    cudaFuncSetAttribute(sgemm_bias, cudaFuncAttributeMaxDynamicSharedMemorySize, gemm_smem);

    rope_tab_k<<<S_, 32>>>(ct, st);

    // q_a = x @ wq_a^T + b   [4096,2048]x[1536,2048]
    { dim3 g(QL_ / 128, ROWS_ / 128, 1);
      sgemm_bias<<<g, 256, gemm_smem>>>(x, wq_a_w, wq_a_b, qa, ROWS_, QL_, H_, 1, 0, 1, 0, 0); }
    rmsnorm_k<<<ROWS_, 256>>>(qa, q_norm_w, QL_);
    // q = q_a @ wq_b^T + b   [4096,1536]x[3072,1536]
    { dim3 g((NH_ * QKH_) / 128, ROWS_ / 128, 1);
      sgemm_bias<<<g, 256, gemm_smem>>>(qa, wq_b_w, wq_b_b, q, ROWS_, NH_ * QKH_, QL_, 1, 0, 1, 0, 0); }
    // kv_full = x @ wkv_a^T + b   [4096,2048]x[576,2048]
    { dim3 g((KVL_ + ROPE_ + 127) / 128, ROWS_ / 128, 1);
      sgemm_bias<<<g, 256, gemm_smem>>>(x, wkv_a_w, wkv_a_b, kvf, ROWS_, KVL_ + ROPE_, H_, 1, 0, 1, 0, 0); }
    kvprep_k<<<ROWS_, 256>>>(kvf, kv_norm_w, kvn, kpe, ct, st);
    ropeq_k<<<(ROWS_ * NH_ * 32) / 256, 256>>>(q, ct, st);

    // absorbed K/V: per (b,h): kvab[z] = kvn[b] (2048x512) @ wkv_b[h] (256x512)^T
    { dim3 g(256 / 128, S_ / 128, B_ * NH_);
      sgemm_bias<<<g, 256, gemm_smem>>>(kvn, wkv_b_w, nullptr, kvab, S_, 256, KVL_,
                             NH_, (long long)S_ * KVL_,
                             NH_, 256LL * KVL_,
                             (long long)S_ * 256); }

    // flash attention (tensor-core, 128-row q-tiles, warp-row-ownership)
    // smem words: sQ 128*196 + sK 64*196 + sVT 128*68 + sP 128*68 = 55040
    // -> 55040*4 = 220,160 B (re-derived from device layout)
    const int attn_smem = (128 * 196 + 64 * 196 + 128 * 68 + 128 * 68) * 4;
    cudaFuncSetAttribute(attn_k, cudaFuncAttributeMaxDynamicSharedMemorySize, attn_smem);
    attn_k<<<dim3(S_ / 128, NH_, B_), 256, attn_smem>>>(q, kvab, kpe, mask, att);

    // out = att @ wo^T + b   [4096,2048]x[2048,2048]
    { dim3 g(H_ / 128, ROWS_ / 128, 1);
      sgemm_bias<<<g, 256, gemm_smem>>>(att, wo_w, wo_b, out, ROWS_, H_, NH_ * VD_, 1, 0, 1, 0, 0); }
}